// round 1
// baseline (speedup 1.0000x reference)
#include <cuda_runtime.h>

// ---------------- problem constants ----------------
#define BB 8
#define CC 256
#define DD 100
#define NN 64          // H*W = 8*8
#define HEADS 8
#define HDIM 32
#define O3 768
#define SLICES (BB*DD) // 800

__device__ float g_xl  [BB*CC*DD*NN];   // conv output        (52.4 MB)
__device__ float g_qkv [BB*O3*DD*NN];   // qkv projection     (157 MB)
__device__ float g_xa  [BB*CC*DD*NN];   // attention output   (52.4 MB)
__device__ float g_wconv[9*CC*CC];      // [k][c][o]
__device__ float g_wqkv [CC*O3];        // [c][o]
__device__ float g_wproj[CC*CC];        // [c][o]

// ---------------- weight transposes (one shot, tiny) ----------------
__global__ void transpose_weights(const float* __restrict__ dw,
                                  const float* __restrict__ qw,
                                  const float* __restrict__ pw) {
    int i = blockIdx.x * blockDim.x + threadIdx.x;
    if (i < 9*CC*CC) {
        int o = i & 255; int c = (i >> 8) & 255; int k = i >> 16;
        g_wconv[i] = dw[(o*CC + c)*9 + k];
    }
    if (i < CC*O3) {
        int o = i % O3; int c = i / O3;
        g_wqkv[i] = qw[o*CC + c];
    }
    if (i < CC*CC) {
        int o = i & 255; int c = i >> 8;
        g_wproj[i] = pw[o*CC + c];
    }
}

// ---------------- conv: 9 shifted GEMMs, per-(b,d) slice ----------------
// grid (4 o-tiles, 800 slices), 64 threads; thread tile 8o x 8n (n-row = h)
__global__ __launch_bounds__(64) void conv_kernel(const float* __restrict__ x,
                                                  const float* __restrict__ bconv) {
    __shared__ float XsP[32][100];   // padded (h+1)*10 + (w+1), zero borders
    __shared__ float Ws[32][64];     // [c][o]

    int s = blockIdx.y; int b = s / DD; int d = s % DD;
    int o_base = blockIdx.x * 64;
    int t = threadIdx.x;
    int oy = t >> 3, tx = t & 7;     // tx = output row h

    float acc[8][8];
    #pragma unroll
    for (int i = 0; i < 8; ++i)
        #pragma unroll
        for (int j = 0; j < 8; ++j) acc[i][j] = 0.f;

    const float* xslice = x + ((long)b*CC*DD + d) * NN;   // + c*6400 + n

    for (int c0 = 0; c0 < CC; c0 += 32) {
        __syncthreads();
        for (int i = t; i < 3200; i += 64) {
            int c = i / 100, p = i % 100;
            int h = p / 10 - 1, w = p % 10 - 1;
            float v = 0.f;
            if ((unsigned)h < 8u && (unsigned)w < 8u)
                v = xslice[(c0 + c)*6400 + h*8 + w];
            XsP[c][p] = v;
        }
        for (int k = 0; k < 9; ++k) {
            int dh = k/3 - 1, dw = k%3 - 1;
            __syncthreads();
            for (int i = t; i < 2048; i += 64) {
                int c = i >> 6, o = i & 63;
                Ws[c][o] = g_wconv[(k*CC + c0 + c)*CC + o_base + o];
            }
            __syncthreads();
            #pragma unroll
            for (int c = 0; c < 32; ++c) {
                float4 w0 = *(const float4*)&Ws[c][oy*8];
                float4 w1 = *(const float4*)&Ws[c][oy*8 + 4];
                const float* xp = &XsP[c][(tx + dh + 1)*10 + dw + 1];
                float xv[8];
                #pragma unroll
                for (int j = 0; j < 8; ++j) xv[j] = xp[j];
                float wv[8] = {w0.x,w0.y,w0.z,w0.w,w1.x,w1.y,w1.z,w1.w};
                #pragma unroll
                for (int i2 = 0; i2 < 8; ++i2)
                    #pragma unroll
                    for (int j = 0; j < 8; ++j)
                        acc[i2][j] += wv[i2]*xv[j];
            }
        }
    }

    float* ysl = g_xl + ((long)b*CC*DD + d) * NN;
    #pragma unroll
    for (int i2 = 0; i2 < 8; ++i2) {
        int o = o_base + oy*8 + i2;
        float bv = bconv[o];
        #pragma unroll
        for (int j = 0; j < 8; ++j)
            ysl[o*6400 + tx*8 + j] = acc[i2][j] + bv;
    }
}

// ---------------- generic 64x64-tile GEMM over slices ----------------
// WHICH==0: Y=g_qkv, X=g_xl, W=g_wqkv   WHICH==1: Y=ext(d_out), X=g_xa, W=g_wproj
template<int OC, int WHICH>
__global__ __launch_bounds__(64) void gemm64(const float* __restrict__ bias,
                                             float* __restrict__ Yext) {
    __shared__ float Xs[32][64];
    __shared__ float Ws[32][64];

    const float* X  = (WHICH == 0) ? g_xl  : g_xa;
    const float* Wt = (WHICH == 0) ? g_wqkv : g_wproj;
    float* Y        = (WHICH == 0) ? g_qkv : Yext;

    int s = blockIdx.y; int b = s / DD; int d = s % DD;
    int o_base = blockIdx.x * 64;
    int t = threadIdx.x;
    int oy = t >> 3, tx = t & 7;

    float acc[8][8];
    #pragma unroll
    for (int i = 0; i < 8; ++i)
        #pragma unroll
        for (int j = 0; j < 8; ++j) acc[i][j] = 0.f;

    const float* xsl = X + ((long)b*CC*DD + d) * NN;

    for (int c0 = 0; c0 < CC; c0 += 32) {
        __syncthreads();
        for (int i = t; i < 2048; i += 64) {
            int c = i >> 6, n = i & 63;
            Xs[c][n] = xsl[(c0 + c)*6400 + n];
            Ws[c][n] = Wt[(c0 + c)*OC + o_base + n];
        }
        __syncthreads();
        #pragma unroll
        for (int c = 0; c < 32; ++c) {
            float4 w0 = *(const float4*)&Ws[c][oy*8];
            float4 w1 = *(const float4*)&Ws[c][oy*8 + 4];
            float4 x0 = *(const float4*)&Xs[c][tx*8];
            float4 x1 = *(const float4*)&Xs[c][tx*8 + 4];
            float wv[8] = {w0.x,w0.y,w0.z,w0.w,w1.x,w1.y,w1.z,w1.w};
            float xv[8] = {x0.x,x0.y,x0.z,x0.w,x1.x,x1.y,x1.z,x1.w};
            #pragma unroll
            for (int i2 = 0; i2 < 8; ++i2)
                #pragma unroll
                for (int j = 0; j < 8; ++j)
                    acc[i2][j] += wv[i2]*xv[j];
        }
    }

    float* ysl = Y + ((long)b*OC*DD + d) * NN;
    #pragma unroll
    for (int i2 = 0; i2 < 8; ++i2) {
        int o = o_base + oy*8 + i2;
        float bv = bias[o];
        #pragma unroll
        for (int j = 0; j < 8; ++j)
            ysl[o*6400 + tx*8 + j] = acc[i2][j] + bv;
    }
}

// ---------------- attention per (b,d,head) window ----------------
// 64 threads, thread t = query position n. scores in registers.
__global__ __launch_bounds__(64) void attn_kernel(const float* __restrict__ rpb) {
    __shared__ float qs[32*64];
    __shared__ float ks[32*64];
    __shared__ float vs[32*64];

    int head = blockIdx.x, d = blockIdx.y, b = blockIdx.z;
    int t = threadIdx.x;

    const float* base = g_qkv + ((long)(b*O3 + head*HDIM)*DD + d) * NN;
    for (int i = t; i < 2048; i += 64) {
        int hd = i >> 6, n = i & 63;
        qs[i] = base[hd*6400 + n];
        ks[i] = base[256*6400 + hd*6400 + n];
        vs[i] = base[512*6400 + hd*6400 + n];
    }
    __syncthreads();

    const int n  = t;
    const int hn = n >> 3, wn = n & 7;
    const float scale = 0.17677669529663687f;  // 32^-0.5

    float qr[32];
    #pragma unroll
    for (int hd = 0; hd < 32; ++hd) qr[hd] = qs[hd*64 + n];

    float sc[64];
    #pragma unroll
    for (int m4 = 0; m4 < 16; ++m4) {
        float a0 = 0, a1 = 0, a2 = 0, a3 = 0;
        #pragma unroll
        for (int hd = 0; hd < 32; ++hd) {
            float4 kk = *(const float4*)&ks[hd*64 + m4*4];
            a0 += qr[hd]*kk.x; a1 += qr[hd]*kk.y;
            a2 += qr[hd]*kk.z; a3 += qr[hd]*kk.w;
        }
        #pragma unroll
        for (int j = 0; j < 4; ++j) {
            int m = m4*4 + j;
            float a = (j==0)?a0:(j==1)?a1:(j==2)?a2:a3;
            int di = hn - (m >> 3) + 7;
            int dj = wn - (m & 7) + 7;
            sc[m] = a*scale + rpb[(di*15 + dj)*HEADS + head];
        }
    }

    float mx = -1e30f;
    #pragma unroll
    for (int m = 0; m < 64; ++m) mx = fmaxf(mx, sc[m]);
    float sum = 0.f;
    #pragma unroll
    for (int m = 0; m < 64; ++m) { sc[m] = __expf(sc[m] - mx); sum += sc[m]; }
    float inv = 1.f / sum;

    float* ysl = g_xa + ((long)(b*CC + head*HDIM)*DD + d) * NN;
    #pragma unroll
    for (int hd = 0; hd < 32; ++hd) {
        float o = 0.f;
        #pragma unroll
        for (int m4 = 0; m4 < 16; ++m4) {
            float4 vv = *(const float4*)&vs[hd*64 + m4*4];
            o += sc[m4*4+0]*vv.x + sc[m4*4+1]*vv.y
               + sc[m4*4+2]*vv.z + sc[m4*4+3]*vv.w;
        }
        ysl[hd*6400 + n] = o * inv;
    }
}

// ---------------- launch ----------------
extern "C" void kernel_launch(void* const* d_in, const int* in_sizes, int n_in,
                              void* d_out, int out_size) {
    const float* x   = (const float*)d_in[0];
    const float* dw  = (const float*)d_in[1];
    const float* dwb = (const float*)d_in[2];
    const float* qw  = (const float*)d_in[3];
    const float* qb  = (const float*)d_in[4];
    const float* pw  = (const float*)d_in[5];
    const float* pb  = (const float*)d_in[6];
    const float* rpb = (const float*)d_in[7];
    float* out = (float*)d_out;

    transpose_weights<<<(9*CC*CC + 255)/256, 256>>>(dw, qw, pw);
    conv_kernel<<<dim3(4, SLICES), 64>>>(x, dwb);
    gemm64<O3, 0><<<dim3(12, SLICES), 64>>>(qb, nullptr);
    attn_kernel<<<dim3(HEADS, DD, BB), 64>>>(rpb);
    gemm64<CC, 1><<<dim3(4, SLICES), 64>>>(pb, out);
}

// round 2
// speedup vs baseline: 1.1741x; 1.1741x over previous
#include <cuda_runtime.h>

// ---------------- problem constants ----------------
#define BB 8
#define CC 256
#define DD 100
#define NN 64          // H*W = 8*8
#define HEADS 8
#define HDIM 32
#define O3 768
#define SLICES (BB*DD) // 800

__device__ float g_xl  [BB*CC*DD*NN];   // conv output
__device__ float g_qkv [BB*O3*DD*NN];   // qkv projection
__device__ float g_xa  [BB*CC*DD*NN];   // attention output
__device__ float g_wconv[9*CC*CC];      // [k][c][o]
__device__ float g_wqkv [CC*O3];        // [c][o]
__device__ float g_wproj[CC*CC];        // [c][o]

// ---------------- packed f32x2 helpers (sm_103a) ----------------
typedef unsigned long long u64t;

__device__ __forceinline__ u64t pk2(float lo, float hi) {
    u64t r; asm("mov.b64 %0,{%1,%2};" : "=l"(r) : "f"(lo), "f"(hi)); return r;
}
__device__ __forceinline__ void fma2(u64t& d, u64t a, u64t b) {
    asm("fma.rn.f32x2 %0,%1,%2,%0;" : "+l"(d) : "l"(a), "l"(b));
}
__device__ __forceinline__ void upk2(u64t v, float& lo, float& hi) {
    asm("mov.b64 {%0,%1},%2;" : "=f"(lo), "=f"(hi) : "l"(v));
}

// ---------------- weight transposes (one shot, tiny) ----------------
__global__ void transpose_weights(const float* __restrict__ dw,
                                  const float* __restrict__ qw,
                                  const float* __restrict__ pw) {
    int i = blockIdx.x * blockDim.x + threadIdx.x;
    if (i < 9*CC*CC) {
        int o = i & 255; int c = (i >> 8) & 255; int k = i >> 16;
        g_wconv[i] = dw[(o*CC + c)*9 + k];
    }
    if (i < CC*O3) {
        int o = i % O3; int c = i / O3;
        g_wqkv[i] = qw[o*CC + c];
    }
    if (i < CC*CC) {
        int o = i & 255; int c = i >> 8;
        g_wproj[i] = pw[o*CC + c];
    }
}

// ---------------- conv: 9 shifted GEMMs, per-(b,d) slice ----------------
// grid (4 o-tiles, 800 slices), 64 threads; thread tile 8o x 8n (n-row = h)
__global__ __launch_bounds__(64) void conv_kernel(const float* __restrict__ x,
                                                  const float* __restrict__ bconv) {
    __shared__ float XsP[32][100];   // padded (h+1)*10 + (w+1), zero borders
    __shared__ float Ws[32][64];     // [c][o]

    int s = blockIdx.y; int b = s / DD; int d = s % DD;
    int o_base = blockIdx.x * 64;
    int t = threadIdx.x;
    int oy = t >> 3, tx = t & 7;     // tx = output row h

    // acc2[i2][j]: i2 = o-pair (o = oy*8 + 2*i2 + {0,1}), j = n within row
    u64t acc2[4][8];
    #pragma unroll
    for (int i = 0; i < 4; ++i)
        #pragma unroll
        for (int j = 0; j < 8; ++j) acc2[i][j] = 0ull;

    const float* xslice = x + ((long)b*CC*DD + d) * NN;   // + c*6400 + n

    for (int c0 = 0; c0 < CC; c0 += 32) {
        __syncthreads();
        for (int i = t; i < 3200; i += 64) {
            int c = i / 100, p = i % 100;
            int h = p / 10 - 1, w = p % 10 - 1;
            float v = 0.f;
            if ((unsigned)h < 8u && (unsigned)w < 8u)
                v = xslice[(c0 + c)*6400 + h*8 + w];
            XsP[c][p] = v;
        }
        for (int k = 0; k < 9; ++k) {
            int dh = k/3 - 1, dw = k%3 - 1;
            __syncthreads();
            for (int i = t; i < 2048; i += 64) {
                int c = i >> 6, o = i & 63;
                Ws[c][o] = g_wconv[(k*CC + c0 + c)*CC + o_base + o];
            }
            __syncthreads();
            #pragma unroll
            for (int c = 0; c < 32; ++c) {
                // weight pairs along o: contiguous in Ws -> free pairing
                ulonglong2 wa = *(const ulonglong2*)&Ws[c][oy*8];
                ulonglong2 wb = *(const ulonglong2*)&Ws[c][oy*8 + 4];
                u64t wp[4] = {wa.x, wa.y, wb.x, wb.y};
                const float* xp = &XsP[c][(tx + dh + 1)*10 + dw + 1];
                u64t xd[8];
                #pragma unroll
                for (int j = 0; j < 8; ++j) { float v = xp[j]; xd[j] = pk2(v, v); }
                #pragma unroll
                for (int i2 = 0; i2 < 4; ++i2)
                    #pragma unroll
                    for (int j = 0; j < 8; ++j)
                        fma2(acc2[i2][j], wp[i2], xd[j]);
            }
        }
    }

    float* ysl = g_xl + ((long)b*CC*DD + d) * NN;
    #pragma unroll
    for (int i2 = 0; i2 < 4; ++i2) {
        int o = o_base + oy*8 + 2*i2;
        float b0 = bconv[o], b1 = bconv[o + 1];
        #pragma unroll
        for (int j = 0; j < 8; ++j) {
            float lo, hi; upk2(acc2[i2][j], lo, hi);
            ysl[o*6400 + tx*8 + j]        = lo + b0;
            ysl[(o + 1)*6400 + tx*8 + j]  = hi + b1;
        }
    }
}

// ---------------- generic 64x64-tile GEMM over slices ----------------
// WHICH==0: Y=g_qkv, X=g_xl, W=g_wqkv   WHICH==1: Y=ext(d_out), X=g_xa, W=g_wproj
template<int OC, int WHICH>
__global__ __launch_bounds__(64) void gemm64(const float* __restrict__ bias,
                                             float* __restrict__ Yext) {
    __shared__ float Xs[32][64];
    __shared__ float Ws[32][64];

    const float* X  = (WHICH == 0) ? g_xl  : g_xa;
    const float* Wt = (WHICH == 0) ? g_wqkv : g_wproj;
    float* Y        = (WHICH == 0) ? g_qkv : Yext;

    int s = blockIdx.y; int b = s / DD; int d = s % DD;
    int o_base = blockIdx.x * 64;
    int t = threadIdx.x;
    int oy = t >> 3, tx = t & 7;

    u64t acc2[4][8];
    #pragma unroll
    for (int i = 0; i < 4; ++i)
        #pragma unroll
        for (int j = 0; j < 8; ++j) acc2[i][j] = 0ull;

    const float* xsl = X + ((long)b*CC*DD + d) * NN;

    for (int c0 = 0; c0 < CC; c0 += 32) {
        __syncthreads();
        for (int i = t; i < 2048; i += 64) {
            int c = i >> 6, n = i & 63;
            Xs[c][n] = xsl[(c0 + c)*6400 + n];
            Ws[c][n] = Wt[(c0 + c)*OC + o_base + n];
        }
        __syncthreads();
        #pragma unroll
        for (int c = 0; c < 32; ++c) {
            ulonglong2 wa = *(const ulonglong2*)&Ws[c][oy*8];
            ulonglong2 wb = *(const ulonglong2*)&Ws[c][oy*8 + 4];
            u64t wp[4] = {wa.x, wa.y, wb.x, wb.y};
            float4 x0 = *(const float4*)&Xs[c][tx*8];
            float4 x1 = *(const float4*)&Xs[c][tx*8 + 4];
            float xv[8] = {x0.x,x0.y,x0.z,x0.w,x1.x,x1.y,x1.z,x1.w};
            u64t xd[8];
            #pragma unroll
            for (int j = 0; j < 8; ++j) xd[j] = pk2(xv[j], xv[j]);
            #pragma unroll
            for (int i2 = 0; i2 < 4; ++i2)
                #pragma unroll
                for (int j = 0; j < 8; ++j)
                    fma2(acc2[i2][j], wp[i2], xd[j]);
        }
    }

    float* ysl = Y + ((long)b*OC*DD + d) * NN;
    #pragma unroll
    for (int i2 = 0; i2 < 4; ++i2) {
        int o = o_base + oy*8 + 2*i2;
        float b0 = bias[o], b1 = bias[o + 1];
        #pragma unroll
        for (int j = 0; j < 8; ++j) {
            float lo, hi; upk2(acc2[i2][j], lo, hi);
            ysl[o*6400 + tx*8 + j]       = lo + b0;
            ysl[(o + 1)*6400 + tx*8 + j] = hi + b1;
        }
    }
}

// ---------------- attention per (b,d,head) window ----------------
// 64 threads, thread t = query position n. scores in registers.
__global__ __launch_bounds__(64) void attn_kernel(const float* __restrict__ rpb) {
    __shared__ float qs[32*64];
    __shared__ float ks[32*64];
    __shared__ float vs[32*64];

    int head = blockIdx.x, d = blockIdx.y, b = blockIdx.z;
    int t = threadIdx.x;

    const float* base = g_qkv + ((long)(b*O3 + head*HDIM)*DD + d) * NN;
    for (int i = t; i < 2048; i += 64) {
        int hd = i >> 6, n = i & 63;
        qs[i] = base[hd*6400 + n];
        ks[i] = base[256*6400 + hd*6400 + n];
        vs[i] = base[512*6400 + hd*6400 + n];
    }
    __syncthreads();

    const int n  = t;
    const int hn = n >> 3, wn = n & 7;
    const float scale = 0.17677669529663687f;  // 32^-0.5

    float qr[32];
    #pragma unroll
    for (int hd = 0; hd < 32; ++hd) qr[hd] = qs[hd*64 + n];

    float sc[64];
    #pragma unroll
    for (int m4 = 0; m4 < 16; ++m4) {
        float a0 = 0, a1 = 0, a2 = 0, a3 = 0;
        #pragma unroll
        for (int hd = 0; hd < 32; ++hd) {
            float4 kk = *(const float4*)&ks[hd*64 + m4*4];
            a0 += qr[hd]*kk.x; a1 += qr[hd]*kk.y;
            a2 += qr[hd]*kk.z; a3 += qr[hd]*kk.w;
        }
        #pragma unroll
        for (int j = 0; j < 4; ++j) {
            int m = m4*4 + j;
            float a = (j==0)?a0:(j==1)?a1:(j==2)?a2:a3;
            int di = hn - (m >> 3) + 7;
            int dj = wn - (m & 7) + 7;
            sc[m] = a*scale + rpb[(di*15 + dj)*HEADS + head];
        }
    }

    float mx = -1e30f;
    #pragma unroll
    for (int m = 0; m < 64; ++m) mx = fmaxf(mx, sc[m]);
    float sum = 0.f;
    #pragma unroll
    for (int m = 0; m < 64; ++m) { sc[m] = __expf(sc[m] - mx); sum += sc[m]; }
    float inv = 1.f / sum;

    float* ysl = g_xa + ((long)(b*CC + head*HDIM)*DD + d) * NN;
    #pragma unroll
    for (int hd = 0; hd < 32; ++hd) {
        float o = 0.f;
        #pragma unroll
        for (int m4 = 0; m4 < 16; ++m4) {
            float4 vv = *(const float4*)&vs[hd*64 + m4*4];
            o += sc[m4*4+0]*vv.x + sc[m4*4+1]*vv.y
               + sc[m4*4+2]*vv.z + sc[m4*4+3]*vv.w;
        }
        ysl[hd*6400 + n] = o * inv;
    }
}

// ---------------- launch ----------------
extern "C" void kernel_launch(void* const* d_in, const int* in_sizes, int n_in,
                              void* d_out, int out_size) {
    const float* x   = (const float*)d_in[0];
    const float* dw  = (const float*)d_in[1];
    const float* dwb = (const float*)d_in[2];
    const float* qw  = (const float*)d_in[3];
    const float* qb  = (const float*)d_in[4];
    const float* pw  = (const float*)d_in[5];
    const float* pb  = (const float*)d_in[6];
    const float* rpb = (const float*)d_in[7];
    float* out = (float*)d_out;

    transpose_weights<<<(9*CC*CC + 255)/256, 256>>>(dw, qw, pw);
    conv_kernel<<<dim3(4, SLICES), 64>>>(x, dwb);
    gemm64<O3, 0><<<dim3(12, SLICES), 64>>>(qb, nullptr);
    attn_kernel<<<dim3(HEADS, DD, BB), 64>>>(rpb);
    gemm64<CC, 1><<<dim3(4, SLICES), 64>>>(pb, out);
}

// round 6
// speedup vs baseline: 2.7292x; 2.3246x over previous
#include <cuda_runtime.h>
#include <cstdint>

// ---------------- problem constants ----------------
#define BB 8
#define CC 256
#define DD 100
#define NN 64
#define HEADS 8
#define HDIM 32
#define O3 768
#define NTOT 6400      // D*N per batch

// ---------------- device scratch (referenced ONLY from device code) ----------------
__device__ float g_xp  [BB*DD*100*CC];   // padded transposed input [b][d][p100][c], tf32-rounded
__device__ float g_xlt [BB*NTOT*CC];     // conv out transposed [b][n][c], tf32-rounded
__device__ float g_qkv [BB*O3*NTOT];     // qkv [b][o][ntot], full fp32
__device__ float g_xat [BB*NTOT*CC];     // attn out transposed [b][n][c], tf32-rounded
__device__ float g_wconv[9*CC*CC];       // [k][o][c], tf32-rounded
__device__ float g_wqc [O3*CC];          // qkv_w tf32-rounded
__device__ float g_wpc [CC*CC];          // proj_w tf32-rounded

// ---------------- helpers ----------------
__device__ __forceinline__ float cvt_tf32(float x) {
    uint32_t u; asm("cvt.rna.tf32.f32 %0, %1;" : "=r"(u) : "f"(x));
    return __uint_as_float(u);
}
__device__ __forceinline__ uint32_t smem_u32(const void* p) {
    uint32_t a;
    asm("{ .reg .u64 t; cvta.to.shared.u64 t, %1; cvt.u32.u64 %0, t; }" : "=r"(a) : "l"(p));
    return a;
}
__device__ __forceinline__ void cpasync16(uint32_t dst, const void* src) {
    asm volatile("cp.async.cg.shared.global [%0], [%1], 16;" :: "r"(dst), "l"(src) : "memory");
}
__device__ __forceinline__ void cp_commit() { asm volatile("cp.async.commit_group;" ::: "memory"); }
__device__ __forceinline__ void cp_wait1()  { asm volatile("cp.async.wait_group 1;" ::: "memory"); }
__device__ __forceinline__ void cp_wait0()  { asm volatile("cp.async.wait_group 0;" ::: "memory"); }

__device__ __forceinline__ void mma_tf32(float c[4], const uint32_t a[4], const uint32_t b[2]) {
    asm volatile(
        "mma.sync.aligned.m16n8k8.row.col.f32.tf32.tf32.f32 "
        "{%0,%1,%2,%3}, {%4,%5,%6,%7}, {%8,%9}, {%0,%1,%2,%3};"
        : "+f"(c[0]), "+f"(c[1]), "+f"(c[2]), "+f"(c[3])
        : "r"(a[0]), "r"(a[1]), "r"(a[2]), "r"(a[3]), "r"(b[0]), "r"(b[1]));
}

// smem: A/B tiles 128 rows x 16 k, row stride 20 floats (conflict-free fragment LDS)
#define TSTRIDE 20
#define TILE_F  (128*TSTRIDE)          // 2560 floats = 10240 B
#define SMEM_TOTAL_B (4*TILE_F*4)      // 40960 B  (<= 48KB default, no opt-in needed)

// warp-tile MMA over one staged 128x16 chunk pair
__device__ __forceinline__ void compute_chunk(const float* As, const float* Bs,
                                              int wm, int wn, int lane,
                                              float acc[4][4][4]) {
    int lr = lane >> 2, lc = lane & 3;
    #pragma unroll
    for (int ks = 0; ks < 2; ++ks) {
        int k0 = ks*8;
        uint32_t a[4][4];
        #pragma unroll
        for (int mi = 0; mi < 4; ++mi) {
            int rb = wm + mi*16 + lr;
            a[mi][0] = __float_as_uint(As[rb*TSTRIDE + k0 + lc]);
            a[mi][1] = __float_as_uint(As[(rb+8)*TSTRIDE + k0 + lc]);
            a[mi][2] = __float_as_uint(As[rb*TSTRIDE + k0 + lc + 4]);
            a[mi][3] = __float_as_uint(As[(rb+8)*TSTRIDE + k0 + lc + 4]);
        }
        uint32_t bf[4][2];
        #pragma unroll
        for (int nj = 0; nj < 4; ++nj) {
            int cb = wn + nj*8 + lr;
            bf[nj][0] = __float_as_uint(Bs[cb*TSTRIDE + k0 + lc]);
            bf[nj][1] = __float_as_uint(Bs[cb*TSTRIDE + k0 + lc + 4]);
        }
        #pragma unroll
        for (int mi = 0; mi < 4; ++mi)
            #pragma unroll
            for (int nj = 0; nj < 4; ++nj)
                mma_tf32(acc[mi][nj], a[mi], bf[nj]);
    }
}

// ================= pre-passes =================
__global__ void prep_weights(const float* __restrict__ dw,
                             const float* __restrict__ qw,
                             const float* __restrict__ pw) {
    int i = blockIdx.x * blockDim.x + threadIdx.x;
    if (i < 9*CC*CC) {
        int c = i & 255, o = (i >> 8) & 255, k = i >> 16;
        g_wconv[i] = cvt_tf32(dw[(o*CC + c)*9 + k]);
    }
    if (i < O3*CC) g_wqc[i] = cvt_tf32(qw[i]);
    if (i < CC*CC) g_wpc[i] = cvt_tf32(pw[i]);
}

// build g_xp [b][d][p=100][c] padded-transposed (tf32-rounded) from x [b][c][d][64]
__global__ __launch_bounds__(256) void pad_transpose(const float* __restrict__ x) {
    __shared__ float Xs[64][65];
    int d = blockIdx.x, b = blockIdx.y, t = threadIdx.x;
    float* outb = g_xp + ((size_t)(b*DD + d)) * 100 * CC;
    for (int cc = 0; cc < 4; ++cc) {
        int c_base = cc * 64;
        __syncthreads();
        for (int v = t; v < 4096; v += 256) {
            int c = v >> 6, n = v & 63;
            Xs[c][n] = x[((size_t)(b*CC + c_base + c)*DD + d)*64 + n];
        }
        __syncthreads();
        for (int v = t; v < 6400; v += 256) {
            int p = v >> 6, c = v & 63;
            int h = p/10 - 1, w = p%10 - 1;
            float val = 0.f;
            if ((unsigned)h < 8u && (unsigned)w < 8u) val = cvt_tf32(Xs[c][h*8 + w]);
            outb[p*CC + c_base + c] = val;
        }
    }
}

// ================= conv via warp MMA =================
__global__ __launch_bounds__(256) void conv_mma(const float* __restrict__ bconv) {
    extern __shared__ float smem[];
    uint32_t sb = smem_u32(smem);
    int tid = threadIdx.x, lane = tid & 31, wid = tid >> 5;
    int wm = (wid & 1) * 64, wn = (wid >> 1) * 32;
    int o_base = blockIdx.x * 128;
    int d0 = blockIdx.y * 2;
    int b = blockIdx.z;

    const float* xpb = g_xp + ((size_t)(b*DD + d0)) * 25600;

    float acc[4][4][4];
    #pragma unroll
    for (int mi = 0; mi < 4; ++mi)
        #pragma unroll
        for (int nj = 0; nj < 4; ++nj)
            #pragma unroll
            for (int q = 0; q < 4; ++q) acc[mi][nj][q] = 0.f;

    auto stage = [&](int chunk, int buf) {
        int k = chunk >> 4, c0 = (chunk & 15) * 16;
        int kh = k / 3, kw = k % 3;
        uint32_t ab = sb + (uint32_t)buf * (2*TILE_F*4);
        uint32_t bbuf = ab + TILE_F*4;
        const float* wkb = g_wconv + k*65536 + (size_t)o_base*256 + c0;
        #pragma unroll
        for (int t = 0; t < 2; ++t) {
            int g = tid + t*256; int row = g >> 2, j = g & 3;
            int dl = row >> 6, n = row & 63, h = n >> 3, w = n & 7;
            int p = (h + kh)*10 + (w + kw);
            cpasync16(ab + row*80 + j*16, xpb + (size_t)dl*25600 + p*256 + c0 + j*4);
            cpasync16(bbuf + row*80 + j*16, wkb + row*256 + j*4);
        }
        cp_commit();
    };

    stage(0, 0);
    for (int i = 0; i < 144; ++i) {
        int buf = i & 1;
        if (i < 143) stage(i + 1, buf ^ 1);
        if (i < 143) cp_wait1(); else cp_wait0();
        __syncthreads();
        compute_chunk(smem + buf*(2*TILE_F), smem + buf*(2*TILE_F) + TILE_F, wm, wn, lane, acc);
        __syncthreads();
    }

    int lr = lane >> 2, lc = lane & 3;
    #pragma unroll
    for (int mi = 0; mi < 4; ++mi) {
        int m = wm + mi*16 + lr;
        int ng0 = (d0 + (m >> 6))*64 + (m & 63);
        int ng1 = (d0 + ((m+8) >> 6))*64 + ((m+8) & 63);
        float* r0 = g_xlt + ((size_t)(b*NTOT + ng0))*CC + o_base;
        float* r1 = g_xlt + ((size_t)(b*NTOT + ng1))*CC + o_base;
        #pragma unroll
        for (int nj = 0; nj < 4; ++nj) {
            int o = wn + nj*8 + lc*2;
            float bv0 = bconv[o_base + o], bv1 = bconv[o_base + o + 1];
            float2 v0 = { cvt_tf32(acc[mi][nj][0] + bv0), cvt_tf32(acc[mi][nj][1] + bv1) };
            float2 v1 = { cvt_tf32(acc[mi][nj][2] + bv0), cvt_tf32(acc[mi][nj][3] + bv1) };
            *(float2*)(r0 + o) = v0;
            *(float2*)(r1 + o) = v1;
        }
    }
}

// ================= projection GEMM via warp MMA =================
// WHICH==0: A=g_wqc (O3 rows), B=g_xlt, Y=g_qkv.  WHICH==1: A=g_wpc, B=g_xat, Y=Yext(d_out).
// Operand symbols resolved in DEVICE code — never passed from host.
template<int OC, int WHICH>
__global__ __launch_bounds__(256) void gemm_mma(const float* __restrict__ bias,
                                                float* __restrict__ Yext) {
    extern __shared__ float smem[];
    uint32_t sb = smem_u32(smem);
    int tid = threadIdx.x, lane = tid & 31, wid = tid >> 5;
    int wm = (wid & 1) * 64, wn = (wid >> 1) * 32;
    int o_base = blockIdx.x * 128;
    int n_base = blockIdx.y * 128;
    int b = blockIdx.z;

    const float* Wsym = (WHICH == 0) ? g_wqc : g_wpc;
    const float* Bsym = (WHICH == 0) ? g_xlt : g_xat;
    float* Y          = (WHICH == 0) ? g_qkv : Yext;

    const float* Ap = Wsym + (size_t)o_base*256;
    const float* Bp = Bsym + ((size_t)b*NTOT + n_base)*256;

    float acc[4][4][4];
    #pragma unroll
    for (int mi = 0; mi < 4; ++mi)
        #pragma unroll
        for (int nj = 0; nj < 4; ++nj)
            #pragma unroll
            for (int q = 0; q < 4; ++q) acc[mi][nj][q] = 0.f;

    auto stage = [&](int chunk, int buf) {
        int c0 = chunk * 16;
        uint32_t ab = sb + (uint32_t)buf * (2*TILE_F*4);
        uint32_t bbuf = ab + TILE_F*4;
        #pragma unroll
        for (int t = 0; t < 2; ++t) {
            int g = tid + t*256; int row = g >> 2, j = g & 3;
            cpasync16(ab + row*80 + j*16, Ap + (size_t)row*256 + c0 + j*4);
            cpasync16(bbuf + row*80 + j*16, Bp + (size_t)row*256 + c0 + j*4);
        }
        cp_commit();
    };

    stage(0, 0);
    for (int i = 0; i < 16; ++i) {
        int buf = i & 1;
        if (i < 15) stage(i + 1, buf ^ 1);
        if (i < 15) cp_wait1(); else cp_wait0();
        __syncthreads();
        compute_chunk(smem + buf*(2*TILE_F), smem + buf*(2*TILE_F) + TILE_F, wm, wn, lane, acc);
        __syncthreads();
    }

    int lr = lane >> 2, lc = lane & 3;
    #pragma unroll
    for (int mi = 0; mi < 4; ++mi) {
        int o0 = o_base + wm + mi*16 + lr;
        float bv0 = bias[o0], bv1 = bias[o0 + 8];
        float* y0 = Y + ((size_t)b*OC + o0)*NTOT + n_base;
        float* y1 = Y + ((size_t)b*OC + o0 + 8)*NTOT + n_base;
        #pragma unroll
        for (int nj = 0; nj < 4; ++nj) {
            int col = wn + nj*8 + lc*2;
            float2 v0 = { acc[mi][nj][0] + bv0, acc[mi][nj][1] + bv0 };
            float2 v1 = { acc[mi][nj][2] + bv1, acc[mi][nj][3] + bv1 };
            *(float2*)(y0 + col) = v0;
            *(float2*)(y1 + col) = v1;
        }
    }
}

// ================= attention (fp32; transposed tf32-rounded output) =================
__global__ __launch_bounds__(64) void attn_kernel(const float* __restrict__ rpb) {
    __shared__ float qs[32*64];
    __shared__ float ks[32*64];
    __shared__ float vs[32*64];

    int head = blockIdx.x, d = blockIdx.y, b = blockIdx.z;
    int t = threadIdx.x;

    const float* base = g_qkv + ((size_t)(b*O3 + head*HDIM))*NTOT + d*64;
    for (int i = t; i < 2048; i += 64) {
        int hd = i >> 6, n = i & 63;
        qs[i] = base[(size_t)hd*NTOT + n];
        ks[i] = base[(size_t)(256 + hd)*NTOT + n];
        vs[i] = base[(size_t)(512 + hd)*NTOT + n];
    }
    __syncthreads();

    const int n = t, hn = n >> 3, wn = n & 7;
    const float scale = 0.17677669529663687f;

    float qr[32];
    #pragma unroll
    for (int hd = 0; hd < 32; ++hd) qr[hd] = qs[hd*64 + n];

    float sc[64];
    #pragma unroll
    for (int m4 = 0; m4 < 16; ++m4) {
        float a0 = 0, a1 = 0, a2 = 0, a3 = 0;
        #pragma unroll
        for (int hd = 0; hd < 32; ++hd) {
            float4 kk = *(const float4*)&ks[hd*64 + m4*4];
            a0 += qr[hd]*kk.x; a1 += qr[hd]*kk.y;
            a2 += qr[hd]*kk.z; a3 += qr[hd]*kk.w;
        }
        #pragma unroll
        for (int j = 0; j < 4; ++j) {
            int m = m4*4 + j;
            float a = (j==0)?a0:(j==1)?a1:(j==2)?a2:a3;
            int di = hn - (m >> 3) + 7;
            int dj = wn - (m & 7) + 7;
            sc[m] = a*scale + rpb[(di*15 + dj)*HEADS + head];
        }
    }

    float mx = -1e30f;
    #pragma unroll
    for (int m = 0; m < 64; ++m) mx = fmaxf(mx, sc[m]);
    float sum = 0.f;
    #pragma unroll
    for (int m = 0; m < 64; ++m) { sc[m] = __expf(sc[m] - mx); sum += sc[m]; }
    float inv = 1.f / sum;

    float* ysl = g_xat + ((size_t)(b*NTOT + d*64 + n))*CC + head*HDIM;
    #pragma unroll
    for (int hd4 = 0; hd4 < 8; ++hd4) {
        float4 o4;
        float* op = (float*)&o4;
        #pragma unroll
        for (int q = 0; q < 4; ++q) {
            int hd = hd4*4 + q;
            float o = 0.f;
            #pragma unroll
            for (int m4 = 0; m4 < 16; ++m4) {
                float4 vv = *(const float4*)&vs[hd*64 + m4*4];
                o += sc[m4*4+0]*vv.x + sc[m4*4+1]*vv.y
                   + sc[m4*4+2]*vv.z + sc[m4*4+3]*vv.w;
            }
            op[q] = cvt_tf32(o * inv);
        }
        *(float4*)(ysl + hd4*4) = o4;
    }
}

// ================= launch =================
extern "C" void kernel_launch(void* const* d_in, const int* in_sizes, int n_in,
                              void* d_out, int out_size) {
    const float* x   = (const float*)d_in[0];
    const float* dw  = (const float*)d_in[1];
    const float* dwb = (const float*)d_in[2];
    const float* qb  = (const float*)d_in[4];
    const float* pb  = (const float*)d_in[6];
    const float* rpb = (const float*)d_in[7];
    const float* qw  = (const float*)d_in[3];
    const float* pw  = (const float*)d_in[5];
    float* out = (float*)d_out;

    prep_weights<<<(9*CC*CC + 255)/256, 256>>>(dw, qw, pw);
    pad_transpose<<<dim3(DD, BB), 256>>>(x);
    conv_mma<<<dim3(2, 50, BB), 256, SMEM_TOTAL_B>>>(dwb);
    gemm_mma<O3, 0><<<dim3(6, 50, BB), 256, SMEM_TOTAL_B>>>(qb, nullptr);
    attn_kernel<<<dim3(HEADS, DD, BB), 64>>>(rpb);
    gemm_mma<CC, 1><<<dim3(2, 50, BB), 256, SMEM_TOTAL_B>>>(pb, out);
}

// round 8
// speedup vs baseline: 3.3265x; 1.2189x over previous
#include <cuda_runtime.h>
#include <cstdint>

// ---------------- problem constants ----------------
#define BB 8
#define CC 256
#define DD 100
#define NN 64
#define HEADS 8
#define HDIM 32
#define O3 768
#define NTOT 6400      // D*N per batch

// ---------------- device scratch (referenced ONLY from device code) ----------------
__device__ float g_xp  [BB*DD*100*CC];   // padded transposed input [b][d][p100][c], tf32-rounded
__device__ float g_xlt [BB*NTOT*CC];     // conv out transposed [b][n][c], tf32-rounded
__device__ float g_qkv [BB*O3*NTOT];     // qkv [b][o][ntot], full fp32
__device__ float g_xat [BB*NTOT*CC];     // attn out transposed [b][n][c], tf32-rounded
__device__ float g_wconv[9*CC*CC];       // [k][o][c], tf32-rounded
__device__ float g_wqc [O3*CC];          // qkv_w tf32-rounded
__device__ float g_wpc [CC*CC];          // proj_w tf32-rounded

// ---------------- helpers ----------------
typedef unsigned long long u64t;

__device__ __forceinline__ float cvt_tf32(float x) {
    uint32_t u; asm("cvt.rna.tf32.f32 %0, %1;" : "=r"(u) : "f"(x));
    return __uint_as_float(u);
}
__device__ __forceinline__ uint32_t smem_u32(const void* p) {
    uint32_t a;
    asm("{ .reg .u64 t; cvta.to.shared.u64 t, %1; cvt.u32.u64 %0, t; }" : "=r"(a) : "l"(p));
    return a;
}
__device__ __forceinline__ void cpasync16(uint32_t dst, const void* src) {
    asm volatile("cp.async.cg.shared.global [%0], [%1], 16;" :: "r"(dst), "l"(src) : "memory");
}
__device__ __forceinline__ void cp_commit() { asm volatile("cp.async.commit_group;" ::: "memory"); }
__device__ __forceinline__ void cp_wait1()  { asm volatile("cp.async.wait_group 1;" ::: "memory"); }
__device__ __forceinline__ void cp_wait0()  { asm volatile("cp.async.wait_group 0;" ::: "memory"); }

__device__ __forceinline__ u64t pk2(float lo, float hi) {
    u64t r; asm("mov.b64 %0,{%1,%2};" : "=l"(r) : "f"(lo), "f"(hi)); return r;
}
__device__ __forceinline__ void fma2(u64t& d, u64t a, u64t b) {
    asm("fma.rn.f32x2 %0,%1,%2,%0;" : "+l"(d) : "l"(a), "l"(b));
}
__device__ __forceinline__ void upk2(u64t v, float& lo, float& hi) {
    asm("mov.b64 {%0,%1},%2;" : "=f"(lo), "=f"(hi) : "l"(v));
}

__device__ __forceinline__ void mma_tf32(float c[4], const uint32_t a[4], const uint32_t b[2]) {
    asm volatile(
        "mma.sync.aligned.m16n8k8.row.col.f32.tf32.tf32.f32 "
        "{%0,%1,%2,%3}, {%4,%5,%6,%7}, {%8,%9}, {%0,%1,%2,%3};"
        : "+f"(c[0]), "+f"(c[1]), "+f"(c[2]), "+f"(c[3])
        : "r"(a[0]), "r"(a[1]), "r"(a[2]), "r"(a[3]), "r"(b[0]), "r"(b[1]));
}

// tiles: 128 rows x KC k, row stride KC+4 floats (conflict-free fragment LDS for KC=16,32)
template<int KC> struct TC {
    static constexpr int STR  = KC + 4;
    static constexpr int TF   = 128 * STR;          // floats per tile
    static constexpr int SMEMB = 4 * TF * 4;        // bytes total (2 bufs x A,B)
};

// warp-tile MMA over one staged 128xKC chunk pair
template<int KC>
__device__ __forceinline__ void compute_chunk(const float* As, const float* Bs,
                                              int wm, int wn, int lane,
                                              float acc[4][4][4]) {
    constexpr int STR = TC<KC>::STR;
    int lr = lane >> 2, lc = lane & 3;
    #pragma unroll
    for (int ks = 0; ks < KC/8; ++ks) {
        int k0 = ks*8;
        uint32_t a[4][4];
        #pragma unroll
        for (int mi = 0; mi < 4; ++mi) {
            int rb = wm + mi*16 + lr;
            a[mi][0] = __float_as_uint(As[rb*STR + k0 + lc]);
            a[mi][1] = __float_as_uint(As[(rb+8)*STR + k0 + lc]);
            a[mi][2] = __float_as_uint(As[rb*STR + k0 + lc + 4]);
            a[mi][3] = __float_as_uint(As[(rb+8)*STR + k0 + lc + 4]);
        }
        uint32_t bf[4][2];
        #pragma unroll
        for (int nj = 0; nj < 4; ++nj) {
            int cb = wn + nj*8 + lr;
            bf[nj][0] = __float_as_uint(Bs[cb*STR + k0 + lc]);
            bf[nj][1] = __float_as_uint(Bs[cb*STR + k0 + lc + 4]);
        }
        #pragma unroll
        for (int mi = 0; mi < 4; ++mi)
            #pragma unroll
            for (int nj = 0; nj < 4; ++nj)
                mma_tf32(acc[mi][nj], a[mi], bf[nj]);
    }
}

// ================= pre-passes =================
__global__ void prep_weights(const float* __restrict__ dw,
                             const float* __restrict__ qw,
                             const float* __restrict__ pw) {
    int i = blockIdx.x * blockDim.x + threadIdx.x;
    if (i < 9*CC*CC) {
        int c = i & 255, o = (i >> 8) & 255, k = i >> 16;
        g_wconv[i] = cvt_tf32(dw[(o*CC + c)*9 + k]);
    }
    if (i < O3*CC) g_wqc[i] = cvt_tf32(qw[i]);
    if (i < CC*CC) g_wpc[i] = cvt_tf32(pw[i]);
}

__global__ __launch_bounds__(256) void pad_transpose(const float* __restrict__ x) {
    __shared__ float Xs[64][65];
    int d = blockIdx.x, b = blockIdx.y, t = threadIdx.x;
    float* outb = g_xp + ((size_t)(b*DD + d)) * 100 * CC;
    for (int cc = 0; cc < 4; ++cc) {
        int c_base = cc * 64;
        __syncthreads();
        for (int v = t; v < 4096; v += 256) {
            int c = v >> 6, n = v & 63;
            Xs[c][n] = x[((size_t)(b*CC + c_base + c)*DD + d)*64 + n];
        }
        __syncthreads();
        for (int v = t; v < 6400; v += 256) {
            int p = v >> 6, c = v & 63;
            int h = p/10 - 1, w = p%10 - 1;
            float val = 0.f;
            if ((unsigned)h < 8u && (unsigned)w < 8u) val = cvt_tf32(Xs[c][h*8 + w]);
            outb[p*CC + c_base + c] = val;
        }
    }
}

// ================= conv via warp MMA =================
template<int KC>
__global__ __launch_bounds__(256) void conv_mma(const float* __restrict__ bconv) {
    constexpr int TF = TC<KC>::TF;
    constexpr int ROWB = TC<KC>::STR * 4;       // bytes per smem row
    extern __shared__ float smem[];
    uint32_t sb = smem_u32(smem);
    int tid = threadIdx.x, lane = tid & 31, wid = tid >> 5;
    int wm = (wid & 1) * 64, wn = (wid >> 1) * 32;
    int o_base = blockIdx.x * 128;
    int d0 = blockIdx.y * 2;
    int b = blockIdx.z;

    const float* xpb = g_xp + ((size_t)(b*DD + d0)) * 25600;

    float acc[4][4][4];
    #pragma unroll
    for (int mi = 0; mi < 4; ++mi)
        #pragma unroll
        for (int nj = 0; nj < 4; ++nj)
            #pragma unroll
            for (int q = 0; q < 4; ++q) acc[mi][nj][q] = 0.f;

    constexpr int CPK = 256/KC;   // c-chunks per shift
    auto stage = [&](int chunk, int buf) {
        int k = chunk / CPK, c0 = (chunk % CPK) * KC;
        int kh = k / 3, kw = k % 3;
        uint32_t ab = sb + (uint32_t)buf * (2*TF*4);
        uint32_t bbuf = ab + TF*4;
        const float* wkb = g_wconv + k*65536 + (size_t)o_base*256 + c0;
        #pragma unroll
        for (int t = 0; t < KC/8; ++t) {
            int g = tid + t*256; int row = g / (KC/4), j = g % (KC/4);
            int dl = row >> 6, n = row & 63, h = n >> 3, w = n & 7;
            int p = (h + kh)*10 + (w + kw);
            cpasync16(ab + row*ROWB + j*16, xpb + (size_t)dl*25600 + p*256 + c0 + j*4);
            cpasync16(bbuf + row*ROWB + j*16, wkb + row*256 + j*4);
        }
        cp_commit();
    };

    constexpr int NCH = 9 * CPK;
    stage(0, 0);
    for (int i = 0; i < NCH; ++i) {
        int buf = i & 1;
        if (i < NCH-1) stage(i + 1, buf ^ 1);
        if (i < NCH-1) cp_wait1(); else cp_wait0();
        __syncthreads();
        compute_chunk<KC>(smem + buf*(2*TF), smem + buf*(2*TF) + TF, wm, wn, lane, acc);
        __syncthreads();
    }

    int lr = lane >> 2, lc = lane & 3;
    #pragma unroll
    for (int mi = 0; mi < 4; ++mi) {
        int m = wm + mi*16 + lr;
        int ng0 = (d0 + (m >> 6))*64 + (m & 63);
        int ng1 = (d0 + ((m+8) >> 6))*64 + ((m+8) & 63);
        float* r0 = g_xlt + ((size_t)(b*NTOT + ng0))*CC + o_base;
        float* r1 = g_xlt + ((size_t)(b*NTOT + ng1))*CC + o_base;
        #pragma unroll
        for (int nj = 0; nj < 4; ++nj) {
            int o = wn + nj*8 + lc*2;
            float bv0 = bconv[o_base + o], bv1 = bconv[o_base + o + 1];
            float2 v0 = { cvt_tf32(acc[mi][nj][0] + bv0), cvt_tf32(acc[mi][nj][1] + bv1) };
            float2 v1 = { cvt_tf32(acc[mi][nj][2] + bv0), cvt_tf32(acc[mi][nj][3] + bv1) };
            *(float2*)(r0 + o) = v0;
            *(float2*)(r1 + o) = v1;
        }
    }
}

// ================= projection GEMM via warp MMA =================
// WHICH==0: A=g_wqc, B=g_xlt, Y=g_qkv.  WHICH==1: A=g_wpc, B=g_xat, Y=Yext(d_out).
template<int OC, int WHICH, int KC>
__global__ __launch_bounds__(256) void gemm_mma(const float* __restrict__ bias,
                                                float* __restrict__ Yext) {
    constexpr int TF = TC<KC>::TF;
    constexpr int ROWB = TC<KC>::STR * 4;
    extern __shared__ float smem[];
    uint32_t sb = smem_u32(smem);
    int tid = threadIdx.x, lane = tid & 31, wid = tid >> 5;
    int wm = (wid & 1) * 64, wn = (wid >> 1) * 32;
    int o_base = blockIdx.x * 128;
    int n_base = blockIdx.y * 128;
    int b = blockIdx.z;

    const float* Wsym = (WHICH == 0) ? g_wqc : g_wpc;
    const float* Bsym = (WHICH == 0) ? g_xlt : g_xat;
    float* Y          = (WHICH == 0) ? g_qkv : Yext;

    const float* Ap = Wsym + (size_t)o_base*256;
    const float* Bp = Bsym + ((size_t)b*NTOT + n_base)*256;

    float acc[4][4][4];
    #pragma unroll
    for (int mi = 0; mi < 4; ++mi)
        #pragma unroll
        for (int nj = 0; nj < 4; ++nj)
            #pragma unroll
            for (int q = 0; q < 4; ++q) acc[mi][nj][q] = 0.f;

    auto stage = [&](int chunk, int buf) {
        int c0 = chunk * KC;
        uint32_t ab = sb + (uint32_t)buf * (2*TF*4);
        uint32_t bbuf = ab + TF*4;
        #pragma unroll
        for (int t = 0; t < KC/8; ++t) {
            int g = tid + t*256; int row = g / (KC/4), j = g % (KC/4);
            cpasync16(ab + row*ROWB + j*16, Ap + (size_t)row*256 + c0 + j*4);
            cpasync16(bbuf + row*ROWB + j*16, Bp + (size_t)row*256 + c0 + j*4);
        }
        cp_commit();
    };

    constexpr int NCH = 256/KC;
    stage(0, 0);
    for (int i = 0; i < NCH; ++i) {
        int buf = i & 1;
        if (i < NCH-1) stage(i + 1, buf ^ 1);
        if (i < NCH-1) cp_wait1(); else cp_wait0();
        __syncthreads();
        compute_chunk<KC>(smem + buf*(2*TF), smem + buf*(2*TF) + TF, wm, wn, lane, acc);
        __syncthreads();
    }

    int lr = lane >> 2, lc = lane & 3;
    #pragma unroll
    for (int mi = 0; mi < 4; ++mi) {
        int o0 = o_base + wm + mi*16 + lr;
        float bv0 = bias[o0], bv1 = bias[o0 + 8];
        float* y0 = Y + ((size_t)b*OC + o0)*NTOT + n_base;
        float* y1 = Y + ((size_t)b*OC + o0 + 8)*NTOT + n_base;
        #pragma unroll
        for (int nj = 0; nj < 4; ++nj) {
            int col = wn + nj*8 + lc*2;
            float2 v0 = { acc[mi][nj][0] + bv0, acc[mi][nj][1] + bv0 };
            float2 v1 = { acc[mi][nj][2] + bv1, acc[mi][nj][3] + bv1 };
            *(float2*)(y0 + col) = v0;
            *(float2*)(y1 + col) = v1;
        }
    }
}

// ================= attention (fp32 math on packed f32x2) =================
__global__ __launch_bounds__(64) void attn_kernel(const float* __restrict__ rpb) {
    __shared__ float qs[2048];
    __shared__ float ks[2048];
    __shared__ float vs[2048];
    __shared__ float rpb_s[225];

    int head = blockIdx.x, d = blockIdx.y, b = blockIdx.z;
    int t = threadIdx.x;

    const float* base = g_qkv + ((size_t)(b*O3 + head*HDIM))*NTOT + d*64;
    for (int i = t; i < 2048; i += 64) {
        int hd = i >> 6, n = i & 63;
        qs[i] = base[(size_t)hd*NTOT + n];
        ks[i] = base[(size_t)(256 + hd)*NTOT + n];
        vs[i] = base[(size_t)(512 + hd)*NTOT + n];
    }
    for (int i = t; i < 225; i += 64) rpb_s[i] = rpb[i*HEADS + head];
    __syncthreads();

    const int n = t, hn = n >> 3, wn = n & 7;
    const float scale = 0.17677669529663687f;

    // scores: hd-outer, packed pairs over m
    u64t acc2[32];
    #pragma unroll
    for (int j = 0; j < 32; ++j) acc2[j] = 0ull;
    #pragma unroll
    for (int hd = 0; hd < 32; ++hd) {
        float qv = qs[hd*64 + n];
        u64t qd = pk2(qv, qv);
        const ulonglong2* kp = (const ulonglong2*)&ks[hd*64];
        #pragma unroll
        for (int m4 = 0; m4 < 16; ++m4) {
            ulonglong2 kk = kp[m4];
            fma2(acc2[m4*2],     qd, kk.x);
            fma2(acc2[m4*2 + 1], qd, kk.y);
        }
    }

    float sc[64];
    #pragma unroll
    for (int j = 0; j < 32; ++j) upk2(acc2[j], sc[2*j], sc[2*j + 1]);
    #pragma unroll
    for (int m = 0; m < 64; ++m) {
        int di = hn - (m >> 3) + 7;
        int dj = wn - (m & 7) + 7;
        sc[m] = sc[m]*scale + rpb_s[di*15 + dj];
    }

    float mx = -1e30f;
    #pragma unroll
    for (int m = 0; m < 64; ++m) mx = fmaxf(mx, sc[m]);
    float sum = 0.f;
    #pragma unroll
    for (int m = 0; m < 64; ++m) { sc[m] = __expf(sc[m] - mx); sum += sc[m]; }
    float inv = 1.f / sum;

    // repack probabilities (inv folded in)
    #pragma unroll
    for (int j = 0; j < 32; ++j) acc2[j] = pk2(sc[2*j]*inv, sc[2*j + 1]*inv);

    float* ysl = g_xat + ((size_t)(b*NTOT + d*64 + n))*CC + head*HDIM;
    #pragma unroll
    for (int hd4 = 0; hd4 < 8; ++hd4) {
        float4 o4;
        float* op = (float*)&o4;
        #pragma unroll
        for (int q = 0; q < 4; ++q) {
            int hd = hd4*4 + q;
            u64t o2 = 0ull;
            const ulonglong2* vp = (const ulonglong2*)&vs[hd*64];
            #pragma unroll
            for (int m4 = 0; m4 < 16; ++m4) {
                ulonglong2 vv = vp[m4];
                fma2(o2, acc2[m4*2],     vv.x);
                fma2(o2, acc2[m4*2 + 1], vv.y);
            }
            float lo, hi; upk2(o2, lo, hi);
            op[q] = cvt_tf32(lo + hi);
        }
        *(float4*)(ysl + hd4*4) = o4;
    }
}

// ================= launch =================
extern "C" void kernel_launch(void* const* d_in, const int* in_sizes, int n_in,
                              void* d_out, int out_size) {
    const float* x   = (const float*)d_in[0];
    const float* dw  = (const float*)d_in[1];
    const float* dwb = (const float*)d_in[2];
    const float* qw  = (const float*)d_in[3];
    const float* qb  = (const float*)d_in[4];
    const float* pw  = (const float*)d_in[5];
    const float* pb  = (const float*)d_in[6];
    const float* rpb = (const float*)d_in[7];
    float* out = (float*)d_out;

    // try to enable 72KB-smem KC=32 variants; fall back to KC=16 if denied
    const int BIG = TC<32>::SMEMB;
    bool big = true;
    big &= cudaFuncSetAttribute(conv_mma<32>, cudaFuncAttributeMaxDynamicSharedMemorySize, BIG) == cudaSuccess;
    big &= cudaFuncSetAttribute(gemm_mma<O3,0,32>, cudaFuncAttributeMaxDynamicSharedMemorySize, BIG) == cudaSuccess;
    big &= cudaFuncSetAttribute(gemm_mma<CC,1,32>, cudaFuncAttributeMaxDynamicSharedMemorySize, BIG) == cudaSuccess;

    prep_weights<<<(9*CC*CC + 255)/256, 256>>>(dw, qw, pw);
    pad_transpose<<<dim3(DD, BB), 256>>>(x);
    if (big) {
        conv_mma<32><<<dim3(2, 50, BB), 256, BIG>>>(dwb);
        gemm_mma<O3,0,32><<<dim3(6, 50, BB), 256, BIG>>>(qb, nullptr);
    } else {
        conv_mma<16><<<dim3(2, 50, BB), 256, TC<16>::SMEMB>>>(dwb);
        gemm_mma<O3,0,16><<<dim3(6, 50, BB), 256, TC<16>::SMEMB>>>(qb, nullptr);
    }
    attn_kernel<<<dim3(HEADS, DD, BB), 64>>>(rpb);
    if (big) {
        gemm_mma<CC,1,32><<<dim3(2, 50, BB), 256, BIG>>>(pb, out);
    } else {
        gemm_mma<CC,1,16><<<dim3(2, 50, BB), 256, TC<16>::SMEMB>>>(pb, out);
    }
}

// round 10
// speedup vs baseline: 5.0511x; 1.5184x over previous
#include <cuda_runtime.h>
#include <cuda_fp16.h>
#include <cstdint>

// ---------------- problem constants ----------------
#define BB 8
#define CC 256
#define DD 100
#define NN 64
#define HEADS 8
#define HDIM 32
#define O3 768
#define NTOT 6400      // D*N per batch

// ---------------- device scratch (referenced ONLY from device code) ----------------
__device__ __half g_xp  [BB*DD*100*CC];  // padded transposed input [b][d][p100][c]
__device__ __half g_xlt [BB*NTOT*CC];    // conv out transposed [b][n][c]
__device__ float  g_qkv [BB*O3*NTOT];    // qkv [b][o][ntot], full fp32
__device__ __half g_xat [BB*NTOT*CC];    // attn out transposed [b][n][c]
__device__ __half g_wconv[9*CC*CC];      // [k][o][c]
__device__ __half g_wqc [O3*CC];         // qkv_w
__device__ __half g_wpc [CC*CC];         // proj_w

// ---------------- helpers ----------------
typedef unsigned long long u64t;

__device__ __forceinline__ uint32_t smem_u32(const void* p) {
    uint32_t a;
    asm("{ .reg .u64 t; cvta.to.shared.u64 t, %1; cvt.u32.u64 %0, t; }" : "=r"(a) : "l"(p));
    return a;
}
__device__ __forceinline__ void cpasync16(uint32_t dst, const void* src) {
    asm volatile("cp.async.cg.shared.global [%0], [%1], 16;" :: "r"(dst), "l"(src) : "memory");
}
__device__ __forceinline__ void cp_commit() { asm volatile("cp.async.commit_group;" ::: "memory"); }
__device__ __forceinline__ void cp_wait1()  { asm volatile("cp.async.wait_group 1;" ::: "memory"); }
__device__ __forceinline__ void cp_wait0()  { asm volatile("cp.async.wait_group 0;" ::: "memory"); }

__device__ __forceinline__ u64t pk2(float lo, float hi) {
    u64t r; asm("mov.b64 %0,{%1,%2};" : "=l"(r) : "f"(lo), "f"(hi)); return r;
}
__device__ __forceinline__ void fma2(u64t& d, u64t a, u64t b) {
    asm("fma.rn.f32x2 %0,%1,%2,%0;" : "+l"(d) : "l"(a), "l"(b));
}
__device__ __forceinline__ void upk2(u64t v, float& lo, float& hi) {
    asm("mov.b64 {%0,%1},%2;" : "=f"(lo), "=f"(hi) : "l"(v));
}

__device__ __forceinline__ void mma_f16(float c[4], const uint32_t a[4], const uint32_t b[2]) {
    asm volatile(
        "mma.sync.aligned.m16n8k16.row.col.f32.f16.f16.f32 "
        "{%0,%1,%2,%3}, {%4,%5,%6,%7}, {%8,%9}, {%0,%1,%2,%3};"
        : "+f"(c[0]), "+f"(c[1]), "+f"(c[2]), "+f"(c[3])
        : "r"(a[0]), "r"(a[1]), "r"(a[2]), "r"(a[3]), "r"(b[0]), "r"(b[1]));
}

// tiles: 128 rows x KC halves; row stride KC+8 halves (16B-aligned rows, conflict-free
// fragment LDS: KC=64 -> bank (4*row+lc)%32 permutation; KC=32 -> (20*row+lc)%32 permutation)
template<int KC> struct TC {
    static constexpr int STRH  = KC + 8;            // halves per smem row
    static constexpr int TFH   = 128 * STRH;        // halves per tile
    static constexpr int SMEMB = 4 * TFH * 2;       // bytes (2 bufs x A,B)
};

// warp-tile MMA over one staged 128xKC half chunk pair
template<int KC>
__device__ __forceinline__ void compute_chunk(const __half* As, const __half* Bs,
                                              int wm, int wn, int lane,
                                              float acc[4][4][4]) {
    constexpr int STRH = TC<KC>::STRH;
    int lr = lane >> 2, lc = lane & 3;
    #pragma unroll
    for (int ks = 0; ks < KC/16; ++ks) {
        int k0 = ks*16;
        uint32_t a[4][4];
        #pragma unroll
        for (int mi = 0; mi < 4; ++mi) {
            int rb = wm + mi*16 + lr;
            a[mi][0] = *(const uint32_t*)&As[rb*STRH + k0 + 2*lc];
            a[mi][1] = *(const uint32_t*)&As[(rb+8)*STRH + k0 + 2*lc];
            a[mi][2] = *(const uint32_t*)&As[rb*STRH + k0 + 2*lc + 8];
            a[mi][3] = *(const uint32_t*)&As[(rb+8)*STRH + k0 + 2*lc + 8];
        }
        uint32_t bf[4][2];
        #pragma unroll
        for (int nj = 0; nj < 4; ++nj) {
            int cb = wn + nj*8 + lr;
            bf[nj][0] = *(const uint32_t*)&Bs[cb*STRH + k0 + 2*lc];
            bf[nj][1] = *(const uint32_t*)&Bs[cb*STRH + k0 + 2*lc + 8];
        }
        #pragma unroll
        for (int mi = 0; mi < 4; ++mi)
            #pragma unroll
            for (int nj = 0; nj < 4; ++nj)
                mma_f16(acc[mi][nj], a[mi], bf[nj]);
    }
}

// ================= pre-passes =================
__global__ void prep_weights(const float* __restrict__ dw,
                             const float* __restrict__ qw,
                             const float* __restrict__ pw) {
    int i = blockIdx.x * blockDim.x + threadIdx.x;
    if (i < 9*CC*CC) {
        int c = i & 255, o = (i >> 8) & 255, k = i >> 16;
        g_wconv[i] = __float2half(dw[(o*CC + c)*9 + k]);
    }
    if (i < O3*CC) g_wqc[i] = __float2half(qw[i]);
    if (i < CC*CC) g_wpc[i] = __float2half(pw[i]);
}

__global__ __launch_bounds__(256) void pad_transpose(const float* __restrict__ x) {
    __shared__ float Xs[64][65];
    int d = blockIdx.x, b = blockIdx.y, t = threadIdx.x;
    __half* outb = g_xp + ((size_t)(b*DD + d)) * 100 * CC;
    for (int cc = 0; cc < 4; ++cc) {
        int c_base = cc * 64;
        __syncthreads();
        for (int v = t; v < 4096; v += 256) {
            int c = v >> 6, n = v & 63;
            Xs[c][n] = x[((size_t)(b*CC + c_base + c)*DD + d)*64 + n];
        }
        __syncthreads();
        for (int v = t; v < 6400; v += 256) {
            int p = v >> 6, c = v & 63;
            int h = p/10 - 1, w = p%10 - 1;
            float val = 0.f;
            if ((unsigned)h < 8u && (unsigned)w < 8u) val = Xs[c][h*8 + w];
            outb[p*CC + c_base + c] = __float2half(val);
        }
    }
}

// ================= conv via fp16 warp MMA =================
template<int KC>
__global__ __launch_bounds__(256) void conv_mma(const float* __restrict__ bconv) {
    constexpr int TFH  = TC<KC>::TFH;
    constexpr int ROWB = TC<KC>::STRH * 2;
    extern __shared__ __half smemh[];
    uint32_t sb = smem_u32(smemh);
    int tid = threadIdx.x, lane = tid & 31, wid = tid >> 5;
    int wm = (wid & 1) * 64, wn = (wid >> 1) * 32;
    int o_base = blockIdx.x * 128;
    int d0 = blockIdx.y * 2;
    int b = blockIdx.z;

    const __half* xpb = g_xp + ((size_t)(b*DD + d0)) * 25600;

    float acc[4][4][4];
    #pragma unroll
    for (int mi = 0; mi < 4; ++mi)
        #pragma unroll
        for (int nj = 0; nj < 4; ++nj)
            #pragma unroll
            for (int q = 0; q < 4; ++q) acc[mi][nj][q] = 0.f;

    constexpr int CPK = 256/KC;
    auto stage = [&](int chunk, int buf) {
        int k = chunk / CPK, c0 = (chunk % CPK) * KC;
        int kh = k / 3, kw = k % 3;
        uint32_t ab = sb + (uint32_t)buf * (2*TFH*2);
        uint32_t bbuf = ab + TFH*2;
        const __half* wkb = g_wconv + k*65536 + (size_t)o_base*256 + c0;
        #pragma unroll
        for (int t = 0; t < KC/16; ++t) {          // 128 rows x (KC/8) 16B-segments / 256 thr
            int g = tid + t*256; int row = g / (KC/8), j = g % (KC/8);
            int dl = row >> 6, n = row & 63, h = n >> 3, w = n & 7;
            int p = (h + kh)*10 + (w + kw);
            cpasync16(ab + row*ROWB + j*16, xpb + (size_t)dl*25600 + p*256 + c0 + j*8);
            cpasync16(bbuf + row*ROWB + j*16, wkb + row*256 + j*8);
        }
        cp_commit();
    };

    constexpr int NCH = 9 * CPK;
    stage(0, 0);
    for (int i = 0; i < NCH; ++i) {
        int buf = i & 1;
        if (i < NCH-1) stage(i + 1, buf ^ 1);
        if (i < NCH-1) cp_wait1(); else cp_wait0();
        __syncthreads();
        compute_chunk<KC>(smemh + buf*(2*TFH), smemh + buf*(2*TFH) + TFH, wm, wn, lane, acc);
        __syncthreads();
    }

    int lr = lane >> 2, lc = lane & 3;
    #pragma unroll
    for (int mi = 0; mi < 4; ++mi) {
        int m = wm + mi*16 + lr;
        int ng0 = (d0 + (m >> 6))*64 + (m & 63);
        int ng1 = (d0 + ((m+8) >> 6))*64 + ((m+8) & 63);
        __half* r0 = g_xlt + ((size_t)(b*NTOT + ng0))*CC + o_base;
        __half* r1 = g_xlt + ((size_t)(b*NTOT + ng1))*CC + o_base;
        #pragma unroll
        for (int nj = 0; nj < 4; ++nj) {
            int o = wn + nj*8 + lc*2;
            float bv0 = bconv[o_base + o], bv1 = bconv[o_base + o + 1];
            *(__half2*)(r0 + o) = __floats2half2_rn(acc[mi][nj][0] + bv0, acc[mi][nj][1] + bv1);
            *(__half2*)(r1 + o) = __floats2half2_rn(acc[mi][nj][2] + bv0, acc[mi][nj][3] + bv1);
        }
    }
}

// ================= projection GEMM via fp16 warp MMA =================
// WHICH==0: A=g_wqc, B=g_xlt, Y=g_qkv(float).  WHICH==1: A=g_wpc, B=g_xat, Y=Yext(d_out float).
template<int OC, int WHICH, int KC>
__global__ __launch_bounds__(256) void gemm_mma(const float* __restrict__ bias,
                                                float* __restrict__ Yext) {
    constexpr int TFH  = TC<KC>::TFH;
    constexpr int ROWB = TC<KC>::STRH * 2;
    extern __shared__ __half smemh[];
    uint32_t sb = smem_u32(smemh);
    int tid = threadIdx.x, lane = tid & 31, wid = tid >> 5;
    int wm = (wid & 1) * 64, wn = (wid >> 1) * 32;
    int o_base = blockIdx.x * 128;
    int n_base = blockIdx.y * 128;
    int b = blockIdx.z;

    const __half* Wsym = (WHICH == 0) ? g_wqc : g_wpc;
    const __half* Bsym = (WHICH == 0) ? g_xlt : g_xat;
    float* Y           = (WHICH == 0) ? g_qkv : Yext;

    const __half* Ap = Wsym + (size_t)o_base*256;
    const __half* Bp = Bsym + ((size_t)b*NTOT + n_base)*256;

    float acc[4][4][4];
    #pragma unroll
    for (int mi = 0; mi < 4; ++mi)
        #pragma unroll
        for (int nj = 0; nj < 4; ++nj)
            #pragma unroll
            for (int q = 0; q < 4; ++q) acc[mi][nj][q] = 0.f;

    auto stage = [&](int chunk, int buf) {
        int c0 = chunk * KC;
        uint32_t ab = sb + (uint32_t)buf * (2*TFH*2);
        uint32_t bbuf = ab + TFH*2;
        #pragma unroll
        for (int t = 0; t < KC/16; ++t) {          // 128 rows x (KC/8) 16B-segments / 256 thr
            int g = tid + t*256; int row = g / (KC/8), j = g % (KC/8);
            cpasync16(ab + row*ROWB + j*16, Ap + (size_t)row*256 + c0 + j*8);
            cpasync16(bbuf + row*ROWB + j*16, Bp + (size_t)row*256 + c0 + j*8);
        }
        cp_commit();
    };

    constexpr int NCH = 256/KC;
    stage(0, 0);
    for (int i = 0; i < NCH; ++i) {
        int buf = i & 1;
        if (i < NCH-1) stage(i + 1, buf ^ 1);
        if (i < NCH-1) cp_wait1(); else cp_wait0();
        __syncthreads();
        compute_chunk<KC>(smemh + buf*(2*TFH), smemh + buf*(2*TFH) + TFH, wm, wn, lane, acc);
        __syncthreads();
    }

    int lr = lane >> 2, lc = lane & 3;
    #pragma unroll
    for (int mi = 0; mi < 4; ++mi) {
        int o0 = o_base + wm + mi*16 + lr;
        float bv0 = bias[o0], bv1 = bias[o0 + 8];
        float* y0 = Y + ((size_t)b*OC + o0)*NTOT + n_base;
        float* y1 = Y + ((size_t)b*OC + o0 + 8)*NTOT + n_base;
        #pragma unroll
        for (int nj = 0; nj < 4; ++nj) {
            int col = wn + nj*8 + lc*2;
            float2 v0 = { acc[mi][nj][0] + bv0, acc[mi][nj][1] + bv0 };
            float2 v1 = { acc[mi][nj][2] + bv1, acc[mi][nj][3] + bv1 };
            *(float2*)(y0 + col) = v0;
            *(float2*)(y1 + col) = v1;
        }
    }
}

// ================= attention (fp32 math on packed f32x2; fp16 output) =================
__global__ __launch_bounds__(64) void attn_kernel(const float* __restrict__ rpb) {
    __shared__ float qs[2048];
    __shared__ float ks[2048];
    __shared__ float vs[2048];
    __shared__ float rpb_s[225];

    int head = blockIdx.x, d = blockIdx.y, b = blockIdx.z;
    int t = threadIdx.x;

    const float* base = g_qkv + ((size_t)(b*O3 + head*HDIM))*NTOT + d*64;
    for (int i = t; i < 2048; i += 64) {
        int hd = i >> 6, n = i & 63;
        qs[i] = base[(size_t)hd*NTOT + n];
        ks[i] = base[(size_t)(256 + hd)*NTOT + n];
        vs[i] = base[(size_t)(512 + hd)*NTOT + n];
    }
    for (int i = t; i < 225; i += 64) rpb_s[i] = rpb[i*HEADS + head];
    __syncthreads();

    const int n = t, hn = n >> 3, wn = n & 7;
    const float scale = 0.17677669529663687f;

    u64t acc2[32];
    #pragma unroll
    for (int j = 0; j < 32; ++j) acc2[j] = 0ull;
    #pragma unroll
    for (int hd = 0; hd < 32; ++hd) {
        float qv = qs[hd*64 + n];
        u64t qd = pk2(qv, qv);
        const ulonglong2* kp = (const ulonglong2*)&ks[hd*64];
        #pragma unroll
        for (int m4 = 0; m4 < 16; ++m4) {
            ulonglong2 kk = kp[m4];
            fma2(acc2[m4*2],     qd, kk.x);
            fma2(acc2[m4*2 + 1], qd, kk.y);
        }
    }

    float sc[64];
    #pragma unroll
    for (int j = 0; j < 32; ++j) upk2(acc2[j], sc[2*j], sc[2*j + 1]);
    #pragma unroll
    for (int m = 0; m < 64; ++m) {
        int di = hn - (m >> 3) + 7;
        int dj = wn - (m & 7) + 7;
        sc[m] = sc[m]*scale + rpb_s[di*15 + dj];
    }

    float mx = -1e30f;
    #pragma unroll
    for (int m = 0; m < 64; ++m) mx = fmaxf(mx, sc[m]);
    float sum = 0.f;
    #pragma unroll
    for (int m = 0; m < 64; ++m) { sc[m] = __expf(sc[m] - mx); sum += sc[m]; }
    float inv = 1.f / sum;

    #pragma unroll
    for (int j = 0; j < 32; ++j) acc2[j] = pk2(sc[2*j]*inv, sc[2*j + 1]*inv);

    __half* ysl = g_xat + ((size_t)(b*NTOT + d*64 + n))*CC + head*HDIM;
    #pragma unroll
    for (int hd4 = 0; hd4 < 8; ++hd4) {
        float op[4];
        #pragma unroll
        for (int q = 0; q < 4; ++q) {
            int hd = hd4*4 + q;
            u64t o2 = 0ull;
            const ulonglong2* vp = (const ulonglong2*)&vs[hd*64];
            #pragma unroll
            for (int m4 = 0; m4 < 16; ++m4) {
                ulonglong2 vv = vp[m4];
                fma2(o2, acc2[m4*2],     vv.x);
                fma2(o2, acc2[m4*2 + 1], vv.y);
            }
            float lo, hi; upk2(o2, lo, hi);
            op[q] = lo + hi;
        }
        *(__half2*)(ysl + hd4*4)     = __floats2half2_rn(op[0], op[1]);
        *(__half2*)(ysl + hd4*4 + 2) = __floats2half2_rn(op[2], op[3]);
    }
}

// ================= launch =================
extern "C" void kernel_launch(void* const* d_in, const int* in_sizes, int n_in,
                              void* d_out, int out_size) {
    const float* x   = (const float*)d_in[0];
    const float* dw  = (const float*)d_in[1];
    const float* dwb = (const float*)d_in[2];
    const float* qw  = (const float*)d_in[3];
    const float* qb  = (const float*)d_in[4];
    const float* pw  = (const float*)d_in[5];
    const float* pb  = (const float*)d_in[6];
    const float* rpb = (const float*)d_in[7];
    float* out = (float*)d_out;

    // try to enable 72KB-smem KC=64 variants; fall back to KC=32 (40KB, no opt-in) if denied
    const int BIG = TC<64>::SMEMB;
    bool big = true;
    big &= cudaFuncSetAttribute(conv_mma<64>, cudaFuncAttributeMaxDynamicSharedMemorySize, BIG) == cudaSuccess;
    big &= cudaFuncSetAttribute(gemm_mma<O3,0,64>, cudaFuncAttributeMaxDynamicSharedMemorySize, BIG) == cudaSuccess;
    big &= cudaFuncSetAttribute(gemm_mma<CC,1,64>, cudaFuncAttributeMaxDynamicSharedMemorySize, BIG) == cudaSuccess;

    prep_weights<<<(9*CC*CC + 255)/256, 256>>>(dw, qw, pw);
    pad_transpose<<<dim3(DD, BB), 256>>>(x);
    if (big) {
        conv_mma<64><<<dim3(2, 50, BB), 256, BIG>>>(dwb);
        gemm_mma<O3,0,64><<<dim3(6, 50, BB), 256, BIG>>>(qb, nullptr);
    } else {
        conv_mma<32><<<dim3(2, 50, BB), 256, TC<32>::SMEMB>>>(dwb);
        gemm_mma<O3,0,32><<<dim3(6, 50, BB), 256, TC<32>::SMEMB>>>(qb, nullptr);
    }
    attn_kernel<<<dim3(HEADS, DD, BB), 64>>>(rpb);
    if (big) {
        gemm_mma<CC,1,64><<<dim3(2, 50, BB), 256, BIG>>>(pb, out);
    } else {
        gemm_mma<CC,1,32><<<dim3(2, 50, BB), 256, TC<32>::SMEMB>>>(pb, out);
    }
}

// round 11
// speedup vs baseline: 5.3259x; 1.0544x over previous
#include <cuda_runtime.h>
#include <cuda_fp16.h>
#include <cstdint>

// ---------------- problem constants ----------------
#define BB 8
#define CC 256
#define DD 100
#define NN 64
#define HEADS 8
#define HDIM 32
#define O3 768
#define NTOT 6400      // D*N per batch

// ---------------- device scratch (referenced ONLY from device code) ----------------
__device__ __half g_xp  [BB*DD*100*CC];  // padded transposed input [b][d][p100][c]
__device__ __half g_xlt [BB*NTOT*CC];    // conv out transposed [b][n][c]
__device__ __half g_qkv [BB*O3*NTOT];    // qkv [b][o][ntot]  (fp16 now)
__device__ __half g_xat [BB*NTOT*CC];    // attn out transposed [b][n][c]
__device__ __half g_wconv[9*CC*CC];      // [k][o][c]
__device__ __half g_wqc [O3*CC];         // qkv_w
__device__ __half g_wpc [CC*CC];         // proj_w

// ---------------- helpers ----------------
typedef unsigned long long u64t;

__device__ __forceinline__ uint32_t smem_u32(const void* p) {
    uint32_t a;
    asm("{ .reg .u64 t; cvta.to.shared.u64 t, %1; cvt.u32.u64 %0, t; }" : "=r"(a) : "l"(p));
    return a;
}
__device__ __forceinline__ void cpasync16(uint32_t dst, const void* src) {
    asm volatile("cp.async.cg.shared.global [%0], [%1], 16;" :: "r"(dst), "l"(src) : "memory");
}
__device__ __forceinline__ void cp_commit() { asm volatile("cp.async.commit_group;" ::: "memory"); }
__device__ __forceinline__ void cp_wait1()  { asm volatile("cp.async.wait_group 1;" ::: "memory"); }
__device__ __forceinline__ void cp_wait0()  { asm volatile("cp.async.wait_group 0;" ::: "memory"); }

__device__ __forceinline__ u64t pk2(float lo, float hi) {
    u64t r; asm("mov.b64 %0,{%1,%2};" : "=l"(r) : "f"(lo), "f"(hi)); return r;
}
__device__ __forceinline__ void fma2(u64t& d, u64t a, u64t b) {
    asm("fma.rn.f32x2 %0,%1,%2,%0;" : "+l"(d) : "l"(a), "l"(b));
}
__device__ __forceinline__ void upk2(u64t v, float& lo, float& hi) {
    asm("mov.b64 {%0,%1},%2;" : "=f"(lo), "=f"(hi) : "l"(v));
}

__device__ __forceinline__ void mma_f16(float c[4], const uint32_t a[4], const uint32_t b[2]) {
    asm volatile(
        "mma.sync.aligned.m16n8k16.row.col.f32.f16.f16.f32 "
        "{%0,%1,%2,%3}, {%4,%5,%6,%7}, {%8,%9}, {%0,%1,%2,%3};"
        : "+f"(c[0]), "+f"(c[1]), "+f"(c[2]), "+f"(c[3])
        : "r"(a[0]), "r"(a[1]), "r"(a[2]), "r"(a[3]), "r"(b[0]), "r"(b[1]));
}
__device__ __forceinline__ void ldsm_x4(uint32_t& r0, uint32_t& r1, uint32_t& r2, uint32_t& r3,
                                        uint32_t addr) {
    asm volatile("ldmatrix.sync.aligned.m8n8.x4.shared.b16 {%0,%1,%2,%3}, [%4];"
                 : "=r"(r0), "=r"(r1), "=r"(r2), "=r"(r3) : "r"(addr));
}

// tiles: 128 rows x KC halves; row stride KC+8 halves (16B-aligned rows; ldmatrix rows at
// 144B (KC=64) / 80B (KC=32) stride -> bank 4r%32 / 20r%32, both 8-row permutations)
template<int KC> struct TC {
    static constexpr int STRH  = KC + 8;            // halves per smem row
    static constexpr int TFH   = 128 * STRH;        // halves per tile
    static constexpr int SMEMB = 4 * TFH * 2;       // bytes (2 bufs x A,B)
};

// warp-tile MMA over one staged 128xKC half chunk pair; ldmatrix fragment loads
template<int KC>
__device__ __forceinline__ void compute_chunk(uint32_t As, uint32_t Bs,
                                              int wm, int wn, int lane,
                                              float acc[4][4][4]) {
    constexpr int STRH = TC<KC>::STRH;
    // A x4: lanes 0-15 -> rows (wm+mi*16 + lane&15), k0; lanes 16-31 -> same rows, k0+8
    int arow = lane & 15, akoff = (lane >> 4) * 8;
    // B x4: lanes 0-7 rows nj*8.., k0; 8-15 same rows k0+8; 16-23 rows +8, k0; 24-31 rows +8, k0+8
    int brow = (lane & 7) + (lane >> 4) * 8, bkoff = ((lane >> 3) & 1) * 8;
    #pragma unroll
    for (int ks = 0; ks < KC/16; ++ks) {
        int k0 = ks*16;
        uint32_t a[4][4];
        #pragma unroll
        for (int mi = 0; mi < 4; ++mi)
            ldsm_x4(a[mi][0], a[mi][1], a[mi][2], a[mi][3],
                    As + (((wm + mi*16 + arow)*STRH) + k0 + akoff)*2);
        uint32_t bf[4][2];
        #pragma unroll
        for (int njp = 0; njp < 2; ++njp)
            ldsm_x4(bf[njp*2][0], bf[njp*2][1], bf[njp*2+1][0], bf[njp*2+1][1],
                    Bs + (((wn + njp*16 + brow)*STRH) + k0 + bkoff)*2);
        #pragma unroll
        for (int mi = 0; mi < 4; ++mi)
            #pragma unroll
            for (int nj = 0; nj < 4; ++nj)
                mma_f16(acc[mi][nj], a[mi], bf[nj]);
    }
}

// ================= pre-passes =================
__global__ void prep_weights(const float* __restrict__ dw,
                             const float* __restrict__ qw,
                             const float* __restrict__ pw) {
    int i = blockIdx.x * blockDim.x + threadIdx.x;
    if (i < 9*CC*CC) {
        int c = i & 255, o = (i >> 8) & 255, k = i >> 16;
        g_wconv[i] = __float2half(dw[(o*CC + c)*9 + k]);
    }
    if (i < O3*CC) g_wqc[i] = __float2half(qw[i]);
    if (i < CC*CC) g_wpc[i] = __float2half(pw[i]);
}

__global__ __launch_bounds__(256) void pad_transpose(const float* __restrict__ x) {
    __shared__ float Xs[64][65];
    int d = blockIdx.x, b = blockIdx.y, t = threadIdx.x;
    __half* outb = g_xp + ((size_t)(b*DD + d)) * 100 * CC;
    for (int cc = 0; cc < 4; ++cc) {
        int c_base = cc * 64;
        __syncthreads();
        for (int v = t; v < 4096; v += 256) {
            int c = v >> 6, n = v & 63;
            Xs[c][n] = x[((size_t)(b*CC + c_base + c)*DD + d)*64 + n];
        }
        __syncthreads();
        for (int v = t; v < 6400; v += 256) {
            int p = v >> 6, c = v & 63;
            int h = p/10 - 1, w = p%10 - 1;
            float val = 0.f;
            if ((unsigned)h < 8u && (unsigned)w < 8u) val = Xs[c][h*8 + w];
            outb[p*CC + c_base + c] = __float2half(val);
        }
    }
}

// ================= conv via fp16 warp MMA =================
template<int KC>
__global__ __launch_bounds__(256) void conv_mma(const float* __restrict__ bconv) {
    constexpr int TFH  = TC<KC>::TFH;
    constexpr int ROWB = TC<KC>::STRH * 2;
    extern __shared__ __half smemh[];
    uint32_t sb = smem_u32(smemh);
    int tid = threadIdx.x, lane = tid & 31, wid = tid >> 5;
    int wm = (wid & 1) * 64, wn = (wid >> 1) * 32;
    int o_base = blockIdx.x * 128;
    int d0 = blockIdx.y * 2;
    int b = blockIdx.z;

    const __half* xpb = g_xp + ((size_t)(b*DD + d0)) * 25600;

    float acc[4][4][4];
    #pragma unroll
    for (int mi = 0; mi < 4; ++mi)
        #pragma unroll
        for (int nj = 0; nj < 4; ++nj)
            #pragma unroll
            for (int q = 0; q < 4; ++q) acc[mi][nj][q] = 0.f;

    constexpr int CPK = 256/KC;
    auto stage = [&](int chunk, int buf) {
        int k = chunk / CPK, c0 = (chunk % CPK) * KC;
        int kh = k / 3, kw = k % 3;
        uint32_t ab = sb + (uint32_t)buf * (2*TFH*2);
        uint32_t bbuf = ab + TFH*2;
        const __half* wkb = g_wconv + k*65536 + (size_t)o_base*256 + c0;
        #pragma unroll
        for (int t = 0; t < KC/16; ++t) {
            int g = tid + t*256; int row = g / (KC/8), j = g % (KC/8);
            int dl = row >> 6, n = row & 63, h = n >> 3, w = n & 7;
            int p = (h + kh)*10 + (w + kw);
            cpasync16(ab + row*ROWB + j*16, xpb + (size_t)dl*25600 + p*256 + c0 + j*8);
            cpasync16(bbuf + row*ROWB + j*16, wkb + row*256 + j*8);
        }
        cp_commit();
    };

    constexpr int NCH = 9 * CPK;
    stage(0, 0);
    for (int i = 0; i < NCH; ++i) {
        int buf = i & 1;
        if (i < NCH-1) stage(i + 1, buf ^ 1);
        if (i < NCH-1) cp_wait1(); else cp_wait0();
        __syncthreads();
        uint32_t ab = sb + (uint32_t)buf * (2*TFH*2);
        compute_chunk<KC>(ab, ab + TFH*2, wm, wn, lane, acc);
        __syncthreads();
    }

    int lr = lane >> 2, lc = lane & 3;
    #pragma unroll
    for (int mi = 0; mi < 4; ++mi) {
        int m = wm + mi*16 + lr;
        int ng0 = (d0 + (m >> 6))*64 + (m & 63);
        int ng1 = (d0 + ((m+8) >> 6))*64 + ((m+8) & 63);
        __half* r0 = g_xlt + ((size_t)(b*NTOT + ng0))*CC + o_base;
        __half* r1 = g_xlt + ((size_t)(b*NTOT + ng1))*CC + o_base;
        #pragma unroll
        for (int nj = 0; nj < 4; ++nj) {
            int o = wn + nj*8 + lc*2;
            float bv0 = bconv[o_base + o], bv1 = bconv[o_base + o + 1];
            *(__half2*)(r0 + o) = __floats2half2_rn(acc[mi][nj][0] + bv0, acc[mi][nj][1] + bv1);
            *(__half2*)(r1 + o) = __floats2half2_rn(acc[mi][nj][2] + bv0, acc[mi][nj][3] + bv1);
        }
    }
}

// ================= projection GEMM via fp16 warp MMA =================
// WHICH==0: A=g_wqc, B=g_xlt, Y=g_qkv(half).  WHICH==1: A=g_wpc, B=g_xat, Y=Yext(d_out float).
template<int OC, int WHICH, int KC>
__global__ __launch_bounds__(256) void gemm_mma(const float* __restrict__ bias,
                                                float* __restrict__ Yext) {
    constexpr int TFH  = TC<KC>::TFH;
    constexpr int ROWB = TC<KC>::STRH * 2;
    extern __shared__ __half smemh[];
    uint32_t sb = smem_u32(smemh);
    int tid = threadIdx.x, lane = tid & 31, wid = tid >> 5;
    int wm = (wid & 1) * 64, wn = (wid >> 1) * 32;
    int o_base = blockIdx.x * 128;
    int n_base = blockIdx.y * 128;
    int b = blockIdx.z;

    const __half* Ap = ((WHICH == 0) ? g_wqc : g_wpc) + (size_t)o_base*256;
    const __half* Bp = ((WHICH == 0) ? g_xlt : g_xat) + ((size_t)b*NTOT + n_base)*256;

    float acc[4][4][4];
    #pragma unroll
    for (int mi = 0; mi < 4; ++mi)
        #pragma unroll
        for (int nj = 0; nj < 4; ++nj)
            #pragma unroll
            for (int q = 0; q < 4; ++q) acc[mi][nj][q] = 0.f;

    auto stage = [&](int chunk, int buf) {
        int c0 = chunk * KC;
        uint32_t ab = sb + (uint32_t)buf * (2*TFH*2);
        uint32_t bbuf = ab + TFH*2;
        #pragma unroll
        for (int t = 0; t < KC/16; ++t) {
            int g = tid + t*256; int row = g / (KC/8), j = g % (KC/8);
            cpasync16(ab + row*ROWB + j*16, Ap + (size_t)row*256 + c0 + j*8);
            cpasync16(bbuf + row*ROWB + j*16, Bp + (size_t)row*256 + c0 + j*8);
        }
        cp_commit();
    };

    constexpr int NCH = 256/KC;
    stage(0, 0);
    for (int i = 0; i < NCH; ++i) {
        int buf = i & 1;
        if (i < NCH-1) stage(i + 1, buf ^ 1);
        if (i < NCH-1) cp_wait1(); else cp_wait0();
        __syncthreads();
        uint32_t ab = sb + (uint32_t)buf * (2*TFH*2);
        compute_chunk<KC>(ab, ab + TFH*2, wm, wn, lane, acc);
        __syncthreads();
    }

    int lr = lane >> 2, lc = lane & 3;
    #pragma unroll
    for (int mi = 0; mi < 4; ++mi) {
        int o0 = o_base + wm + mi*16 + lr;
        float bv0 = bias[o0], bv1 = bias[o0 + 8];
        #pragma unroll
        for (int nj = 0; nj < 4; ++nj) {
            int col = wn + nj*8 + lc*2;
            if (WHICH == 0) {
                __half* y0 = g_qkv + ((size_t)b*OC + o0)*NTOT + n_base;
                __half* y1 = g_qkv + ((size_t)b*OC + o0 + 8)*NTOT + n_base;
                *(__half2*)(y0 + col) = __floats2half2_rn(acc[mi][nj][0] + bv0, acc[mi][nj][1] + bv0);
                *(__half2*)(y1 + col) = __floats2half2_rn(acc[mi][nj][2] + bv1, acc[mi][nj][3] + bv1);
            } else {
                float* y0 = Yext + ((size_t)b*OC + o0)*NTOT + n_base;
                float* y1 = Yext + ((size_t)b*OC + o0 + 8)*NTOT + n_base;
                float2 v0 = { acc[mi][nj][0] + bv0, acc[mi][nj][1] + bv0 };
                float2 v1 = { acc[mi][nj][2] + bv1, acc[mi][nj][3] + bv1 };
                *(float2*)(y0 + col) = v0;
                *(float2*)(y1 + col) = v1;
            }
        }
    }
}

// ================= attention (fp32 math on packed f32x2; fp16 in/out) =================
__global__ __launch_bounds__(64) void attn_kernel(const float* __restrict__ rpb) {
    __shared__ float qs[2048];
    __shared__ float ks[2048];
    __shared__ float vs[2048];
    __shared__ float rpb_s[225];

    int head = blockIdx.x, d = blockIdx.y, b = blockIdx.z;
    int t = threadIdx.x;

    const __half* base = g_qkv + ((size_t)(b*O3 + head*HDIM))*NTOT + d*64;
    for (int i = t; i < 2048; i += 64) {
        int hd = i >> 6, n = i & 63;
        qs[i] = __half2float(base[(size_t)hd*NTOT + n]);
        ks[i] = __half2float(base[(size_t)(256 + hd)*NTOT + n]);
        vs[i] = __half2float(base[(size_t)(512 + hd)*NTOT + n]);
    }
    for (int i = t; i < 225; i += 64) rpb_s[i] = rpb[i*HEADS + head];
    __syncthreads();

    const int n = t, hn = n >> 3, wn = n & 7;
    const float scale = 0.17677669529663687f;

    u64t acc2[32];
    #pragma unroll
    for (int j = 0; j < 32; ++j) acc2[j] = 0ull;
    #pragma unroll
    for (int hd = 0; hd < 32; ++hd) {
        float qv = qs[hd*64 + n];
        u64t qd = pk2(qv, qv);
        const ulonglong2* kp = (const ulonglong2*)&ks[hd*64];
        #pragma unroll
        for (int m4 = 0; m4 < 16; ++m4) {
            ulonglong2 kk = kp[m4];
            fma2(acc2[m4*2],     qd, kk.x);
            fma2(acc2[m4*2 + 1], qd, kk.y);
        }
    }

    float sc[64];
    #pragma unroll
    for (int j = 0; j < 32; ++j) upk2(acc2[j], sc[2*j], sc[2*j + 1]);
    #pragma unroll
    for (int m = 0; m < 64; ++m) {
        int di = hn - (m >> 3) + 7;
        int dj = wn - (m & 7) + 7;
        sc[m] = sc[m]*scale + rpb_s[di*15 + dj];
    }

    float mx = -1e30f;
    #pragma unroll
    for (int m = 0; m < 64; ++m) mx = fmaxf(mx, sc[m]);
    float sum = 0.f;
    #pragma unroll
    for (int m = 0; m < 64; ++m) { sc[m] = __expf(sc[m] - mx); sum += sc[m]; }
    float inv = 1.f / sum;

    #pragma unroll
    for (int j = 0; j < 32; ++j) acc2[j] = pk2(sc[2*j]*inv, sc[2*j + 1]*inv);

    __half* ysl = g_xat + ((size_t)(b*NTOT + d*64 + n))*CC + head*HDIM;
    #pragma unroll
    for (int hd4 = 0; hd4 < 8; ++hd4) {
        float op[4];
        #pragma unroll
        for (int q = 0; q < 4; ++q) {
            int hd = hd4*4 + q;
            u64t o2 = 0ull;
            const ulonglong2* vp = (const ulonglong2*)&vs[hd*64];
            #pragma unroll
            for (int m4 = 0; m4 < 16; ++m4) {
                ulonglong2 vv = vp[m4];
                fma2(o2, acc2[m4*2],     vv.x);
                fma2(o2, acc2[m4*2 + 1], vv.y);
            }
            float lo, hi; upk2(o2, lo, hi);
            op[q] = lo + hi;
        }
        *(__half2*)(ysl + hd4*4)     = __floats2half2_rn(op[0], op[1]);
        *(__half2*)(ysl + hd4*4 + 2) = __floats2half2_rn(op[2], op[3]);
    }
}

// ================= launch =================
extern "C" void kernel_launch(void* const* d_in, const int* in_sizes, int n_in,
                              void* d_out, int out_size) {
    const float* x   = (const float*)d_in[0];
    const float* dw  = (const float*)d_in[1];
    const float* dwb = (const float*)d_in[2];
    const float* qw  = (const float*)d_in[3];
    const float* qb  = (const float*)d_in[4];
    const float* pw  = (const float*)d_in[5];
    const float* pb  = (const float*)d_in[6];
    const float* rpb = (const float*)d_in[7];
    float* out = (float*)d_out;

    // try to enable 72KB-smem KC=64 variants; fall back to KC=32 (40KB, no opt-in) if denied
    const int BIG = TC<64>::SMEMB;
    bool big = true;
    big &= cudaFuncSetAttribute(conv_mma<64>, cudaFuncAttributeMaxDynamicSharedMemorySize, BIG) == cudaSuccess;
    big &= cudaFuncSetAttribute(gemm_mma<O3,0,64>, cudaFuncAttributeMaxDynamicSharedMemorySize, BIG) == cudaSuccess;
    big &= cudaFuncSetAttribute(gemm_mma<CC,1,64>, cudaFuncAttributeMaxDynamicSharedMemorySize, BIG) == cudaSuccess;

    prep_weights<<<(9*CC*CC + 255)/256, 256>>>(dw, qw, pw);
    pad_transpose<<<dim3(DD, BB), 256>>>(x);
    if (big) {
        conv_mma<64><<<dim3(2, 50, BB), 256, BIG>>>(dwb);
        gemm_mma<O3,0,64><<<dim3(6, 50, BB), 256, BIG>>>(qb, nullptr);
    } else {
        conv_mma<32><<<dim3(2, 50, BB), 256, TC<32>::SMEMB>>>(dwb);
        gemm_mma<O3,0,32><<<dim3(6, 50, BB), 256, TC<32>::SMEMB>>>(qb, nullptr);
    }
    attn_kernel<<<dim3(HEADS, DD, BB), 64>>>(rpb);
    if (big) {
        gemm_mma<CC,1,64><<<dim3(2, 50, BB), 256, BIG>>>(pb, out);
    } else {
        gemm_mma<CC,1,32><<<dim3(2, 50, BB), 256, TC<32>::SMEMB>>>(pb, out);
    }
}

// round 12
// speedup vs baseline: 5.6624x; 1.0632x over previous
#include <cuda_runtime.h>
#include <cuda_fp16.h>
#include <cstdint>

// ---------------- problem constants ----------------
#define BB 8
#define CC 256
#define DD 100
#define NN 64
#define HEADS 8
#define HDIM 32
#define O3 768
#define NTOT 6400      // D*N per batch

// ---------------- device scratch (referenced ONLY from device code) ----------------
__device__ __half g_xp  [BB*DD*100*CC];  // padded transposed input [b][d][p100][c]
__device__ __half g_xlt [BB*NTOT*CC];    // conv out transposed [b][n][c]
__device__ __half g_qkv [BB*O3*NTOT];    // qkv [b][o][ntot]
__device__ __half g_xat [BB*NTOT*CC];    // attn out transposed [b][n][c]
__device__ __half g_wconv[9*CC*CC];      // [k][o][c]
__device__ __half g_wqc [O3*CC];         // qkv_w
__device__ __half g_wpc [CC*CC];         // proj_w

// ---------------- helpers ----------------
typedef unsigned long long u64t;

__device__ __forceinline__ uint32_t smem_u32(const void* p) {
    uint32_t a;
    asm("{ .reg .u64 t; cvta.to.shared.u64 t, %1; cvt.u32.u64 %0, t; }" : "=r"(a) : "l"(p));
    return a;
}
__device__ __forceinline__ void cpasync16(uint32_t dst, const void* src) {
    asm volatile("cp.async.cg.shared.global [%0], [%1], 16;" :: "r"(dst), "l"(src) : "memory");
}
__device__ __forceinline__ void cp_commit() { asm volatile("cp.async.commit_group;" ::: "memory"); }
__device__ __forceinline__ void cp_wait1()  { asm volatile("cp.async.wait_group 1;" ::: "memory"); }
__device__ __forceinline__ void cp_wait0()  { asm volatile("cp.async.wait_group 0;" ::: "memory"); }

__device__ __forceinline__ u64t pk2(float lo, float hi) {
    u64t r; asm("mov.b64 %0,{%1,%2};" : "=l"(r) : "f"(lo), "f"(hi)); return r;
}
__device__ __forceinline__ void fma2(u64t& d, u64t a, u64t b) {
    asm("fma.rn.f32x2 %0,%1,%2,%0;" : "+l"(d) : "l"(a), "l"(b));
}
__device__ __forceinline__ void upk2(u64t v, float& lo, float& hi) {
    asm("mov.b64 {%0,%1},%2;" : "=f"(lo), "=f"(hi) : "l"(v));
}

__device__ __forceinline__ void mma_f16(float c[4], const uint32_t a[4], const uint32_t b[2]) {
    asm volatile(
        "mma.sync.aligned.m16n8k16.row.col.f32.f16.f16.f32 "
        "{%0,%1,%2,%3}, {%4,%5,%6,%7}, {%8,%9}, {%0,%1,%2,%3};"
        : "+f"(c[0]), "+f"(c[1]), "+f"(c[2]), "+f"(c[3])
        : "r"(a[0]), "r"(a[1]), "r"(a[2]), "r"(a[3]), "r"(b[0]), "r"(b[1]));
}
__device__ __forceinline__ void ldsm_x4(uint32_t& r0, uint32_t& r1, uint32_t& r2, uint32_t& r3,
                                        uint32_t addr) {
    asm volatile("ldmatrix.sync.aligned.m8n8.x4.shared.b16 {%0,%1,%2,%3}, [%4];"
                 : "=r"(r0), "=r"(r1), "=r"(r2), "=r"(r3) : "r"(addr));
}

// generic GEMM tiles: 128 rows x KC halves; row stride KC+8 halves
template<int KC> struct TC {
    static constexpr int STRH  = KC + 8;
    static constexpr int TFH   = 128 * STRH;
    static constexpr int SMEMB = 4 * TFH * 2;
};

// warp-tile MMA over one staged 128xKC half chunk pair; ldmatrix fragment loads
template<int KC>
__device__ __forceinline__ void compute_chunk(uint32_t As, uint32_t Bs,
                                              int wm, int wn, int lane,
                                              float acc[4][4][4]) {
    constexpr int STRH = TC<KC>::STRH;
    int arow = lane & 15, akoff = (lane >> 4) * 8;
    int brow = (lane & 7) + (lane >> 4) * 8, bkoff = ((lane >> 3) & 1) * 8;
    #pragma unroll
    for (int ks = 0; ks < KC/16; ++ks) {
        int k0 = ks*16;
        uint32_t a[4][4];
        #pragma unroll
        for (int mi = 0; mi < 4; ++mi)
            ldsm_x4(a[mi][0], a[mi][1], a[mi][2], a[mi][3],
                    As + (((wm + mi*16 + arow)*STRH) + k0 + akoff)*2);
        uint32_t bf[4][2];
        #pragma unroll
        for (int njp = 0; njp < 2; ++njp)
            ldsm_x4(bf[njp*2][0], bf[njp*2][1], bf[njp*2+1][0], bf[njp*2+1][1],
                    Bs + (((wn + njp*16 + brow)*STRH) + k0 + bkoff)*2);
        #pragma unroll
        for (int mi = 0; mi < 4; ++mi)
            #pragma unroll
            for (int nj = 0; nj < 4; ++nj)
                mma_f16(acc[mi][nj], a[mi], bf[nj]);
    }
}

// ================= pre-passes =================
__global__ void prep_weights(const float* __restrict__ dw,
                             const float* __restrict__ qw,
                             const float* __restrict__ pw) {
    int i = blockIdx.x * blockDim.x + threadIdx.x;
    if (i < 9*CC*CC) {
        int c = i & 255, o = (i >> 8) & 255, k = i >> 16;
        g_wconv[i] = __float2half(dw[(o*CC + c)*9 + k]);
    }
    if (i < O3*CC) g_wqc[i] = __float2half(qw[i]);
    if (i < CC*CC) g_wpc[i] = __float2half(pw[i]);
}

__global__ __launch_bounds__(256) void pad_transpose(const float* __restrict__ x) {
    __shared__ float Xs[64][65];
    int d = blockIdx.x, b = blockIdx.y, t = threadIdx.x;
    __half* outb = g_xp + ((size_t)(b*DD + d)) * 100 * CC;
    for (int cc = 0; cc < 4; ++cc) {
        int c_base = cc * 64;
        __syncthreads();
        for (int v = t; v < 4096; v += 256) {
            int c = v >> 6, n = v & 63;
            Xs[c][n] = x[((size_t)(b*CC + c_base + c)*DD + d)*64 + n];
        }
        __syncthreads();
        for (int v = t; v < 6400; v += 256) {
            int p = v >> 6, c = v & 63;
            int h = p/10 - 1, w = p%10 - 1;
            float val = 0.f;
            if ((unsigned)h < 8u && (unsigned)w < 8u) val = Xs[c][h*8 + w];
            outb[p*CC + c_base + c] = __float2half(val);
        }
    }
}

// ================= conv v2: resident padded slab + shifted ldmatrix =================
// smem: slab 200 rows x 72 halves (28800 B) | W0 128x72 (18432 B) | W1 (18432 B) = 65664 B
#define CV_STRH 72
#define CV_SLABB 28800
#define CV_WB    18432
#define CV_SMEM  (CV_SLABB + 2*CV_WB)

__global__ __launch_bounds__(256) void conv_mma2(const float* __restrict__ bconv) {
    extern __shared__ __half smemh[];
    uint32_t sb = smem_u32(smemh);
    const uint32_t SLAB = sb, WBUF0 = sb + CV_SLABB, WBUF1 = sb + CV_SLABB + CV_WB;
    int tid = threadIdx.x, lane = tid & 31, wid = tid >> 5;
    int wm = (wid & 1) * 64, wn = (wid >> 1) * 32;
    int o_base = blockIdx.x * 128;
    int d0 = blockIdx.y * 2;
    int b = blockIdx.z;

    const __half* xpb = g_xp + ((size_t)(b*DD + d0)) * 25600;

    // per-lane A base addresses into the slab (row = dl*100 + h*10 + w), shift adds (kh*10+kw)*144
    int arowl = lane & 15, akoff = (lane >> 4) * 8;
    uint32_t abase[4];
    #pragma unroll
    for (int mi = 0; mi < 4; ++mi) {
        int m = wm + mi*16 + arowl;
        int slabrow = (m >> 6)*100 + ((m & 63) >> 3)*10 + (m & 7);
        abase[mi] = SLAB + (slabrow*CV_STRH + akoff)*2;
    }
    int brow = (lane & 7) + (lane >> 4) * 8, bkoff = ((lane >> 3) & 1) * 8;

    float acc[4][4][4];
    #pragma unroll
    for (int mi = 0; mi < 4; ++mi)
        #pragma unroll
        for (int nj = 0; nj < 4; ++nj)
            #pragma unroll
            for (int q = 0; q < 4; ++q) acc[mi][nj][q] = 0.f;

    for (int cc = 0; cc < 4; ++cc) {
        int c0 = cc * 64;
        __syncthreads();                       // prior chunk fully consumed slab + W bufs
        // stage slab: 200 rows x 8 16B-segments = 1600
        #pragma unroll
        for (int t = 0; t < 7; ++t) {
            int s = tid + t*256;
            if (s < 1600) {
                int row = s >> 3, j = s & 7;
                cpasync16(SLAB + row*144 + j*16,
                          xpb + (size_t)(row/100)*25600 + (row%100)*256 + c0 + j*8);
            }
        }
        cp_commit();
        auto stageW = [&](int k, uint32_t wb) {
            const __half* wkb = g_wconv + k*65536 + (size_t)o_base*256 + c0;
            #pragma unroll
            for (int t = 0; t < 4; ++t) {
                int s = tid + t*256; int row = s >> 3, j = s & 7;
                cpasync16(wb + row*144 + j*16, wkb + row*256 + j*8);
            }
            cp_commit();
        };
        stageW(0, WBUF0);
        for (int k = 0; k < 9; ++k) {
            uint32_t wb = (k & 1) ? WBUF1 : WBUF0;
            if (k < 8) stageW(k + 1, (k & 1) ? WBUF0 : WBUF1);
            if (k < 8) cp_wait1(); else cp_wait0();
            __syncthreads();
            uint32_t shoff = (uint32_t)((k/3)*10 + (k%3)) * 144;
            #pragma unroll
            for (int ks = 0; ks < 4; ++ks) {
                int k0 = ks*16;
                uint32_t a[4][4];
                #pragma unroll
                for (int mi = 0; mi < 4; ++mi)
                    ldsm_x4(a[mi][0], a[mi][1], a[mi][2], a[mi][3],
                            abase[mi] + shoff + k0*2);
                uint32_t bf[4][2];
                #pragma unroll
                for (int njp = 0; njp < 2; ++njp)
                    ldsm_x4(bf[njp*2][0], bf[njp*2][1], bf[njp*2+1][0], bf[njp*2+1][1],
                            wb + (((wn + njp*16 + brow)*CV_STRH) + k0 + bkoff)*2);
                #pragma unroll
                for (int mi = 0; mi < 4; ++mi)
                    #pragma unroll
                    for (int nj = 0; nj < 4; ++nj)
                        mma_f16(acc[mi][nj], a[mi], bf[nj]);
            }
            __syncthreads();
        }
    }

    int lr = lane >> 2, lc = lane & 3;
    #pragma unroll
    for (int mi = 0; mi < 4; ++mi) {
        int m = wm + mi*16 + lr;
        int ng0 = (d0 + (m >> 6))*64 + (m & 63);
        int ng1 = (d0 + ((m+8) >> 6))*64 + ((m+8) & 63);
        __half* r0 = g_xlt + ((size_t)(b*NTOT + ng0))*CC + o_base;
        __half* r1 = g_xlt + ((size_t)(b*NTOT + ng1))*CC + o_base;
        #pragma unroll
        for (int nj = 0; nj < 4; ++nj) {
            int o = wn + nj*8 + lc*2;
            float bv0 = bconv[o_base + o], bv1 = bconv[o_base + o + 1];
            *(__half2*)(r0 + o) = __floats2half2_rn(acc[mi][nj][0] + bv0, acc[mi][nj][1] + bv1);
            *(__half2*)(r1 + o) = __floats2half2_rn(acc[mi][nj][2] + bv0, acc[mi][nj][3] + bv1);
        }
    }
}

// ================= conv fallback (KC=32, 40KB smem) =================
template<int KC>
__global__ __launch_bounds__(256) void conv_mma(const float* __restrict__ bconv) {
    constexpr int TFH  = TC<KC>::TFH;
    constexpr int ROWB = TC<KC>::STRH * 2;
    extern __shared__ __half smemh[];
    uint32_t sb = smem_u32(smemh);
    int tid = threadIdx.x, lane = tid & 31, wid = tid >> 5;
    int wm = (wid & 1) * 64, wn = (wid >> 1) * 32;
    int o_base = blockIdx.x * 128;
    int d0 = blockIdx.y * 2;
    int b = blockIdx.z;

    const __half* xpb = g_xp + ((size_t)(b*DD + d0)) * 25600;

    float acc[4][4][4];
    #pragma unroll
    for (int mi = 0; mi < 4; ++mi)
        #pragma unroll
        for (int nj = 0; nj < 4; ++nj)
            #pragma unroll
            for (int q = 0; q < 4; ++q) acc[mi][nj][q] = 0.f;

    constexpr int CPK = 256/KC;
    auto stage = [&](int chunk, int buf) {
        int k = chunk / CPK, c0 = (chunk % CPK) * KC;
        int kh = k / 3, kw = k % 3;
        uint32_t ab = sb + (uint32_t)buf * (2*TFH*2);
        uint32_t bbuf = ab + TFH*2;
        const __half* wkb = g_wconv + k*65536 + (size_t)o_base*256 + c0;
        #pragma unroll
        for (int t = 0; t < KC/16; ++t) {
            int g = tid + t*256; int row = g / (KC/8), j = g % (KC/8);
            int dl = row >> 6, n = row & 63, h = n >> 3, w = n & 7;
            int p = (h + kh)*10 + (w + kw);
            cpasync16(ab + row*ROWB + j*16, xpb + (size_t)dl*25600 + p*256 + c0 + j*8);
            cpasync16(bbuf + row*ROWB + j*16, wkb + row*256 + j*8);
        }
        cp_commit();
    };

    constexpr int NCH = 9 * CPK;
    stage(0, 0);
    for (int i = 0; i < NCH; ++i) {
        int buf = i & 1;
        if (i < NCH-1) stage(i + 1, buf ^ 1);
        if (i < NCH-1) cp_wait1(); else cp_wait0();
        __syncthreads();
        uint32_t ab = sb + (uint32_t)buf * (2*TFH*2);
        compute_chunk<KC>(ab, ab + TFH*2, wm, wn, lane, acc);
        __syncthreads();
    }

    int lr = lane >> 2, lc = lane & 3;
    #pragma unroll
    for (int mi = 0; mi < 4; ++mi) {
        int m = wm + mi*16 + lr;
        int ng0 = (d0 + (m >> 6))*64 + (m & 63);
        int ng1 = (d0 + ((m+8) >> 6))*64 + ((m+8) & 63);
        __half* r0 = g_xlt + ((size_t)(b*NTOT + ng0))*CC + o_base;
        __half* r1 = g_xlt + ((size_t)(b*NTOT + ng1))*CC + o_base;
        #pragma unroll
        for (int nj = 0; nj < 4; ++nj) {
            int o = wn + nj*8 + lc*2;
            float bv0 = bconv[o_base + o], bv1 = bconv[o_base + o + 1];
            *(__half2*)(r0 + o) = __floats2half2_rn(acc[mi][nj][0] + bv0, acc[mi][nj][1] + bv1);
            *(__half2*)(r1 + o) = __floats2half2_rn(acc[mi][nj][2] + bv0, acc[mi][nj][3] + bv1);
        }
    }
}

// ================= projection GEMM via fp16 warp MMA =================
template<int OC, int WHICH, int KC>
__global__ __launch_bounds__(256) void gemm_mma(const float* __restrict__ bias,
                                                float* __restrict__ Yext) {
    constexpr int TFH  = TC<KC>::TFH;
    constexpr int ROWB = TC<KC>::STRH * 2;
    extern __shared__ __half smemh[];
    uint32_t sb = smem_u32(smemh);
    int tid = threadIdx.x, lane = tid & 31, wid = tid >> 5;
    int wm = (wid & 1) * 64, wn = (wid >> 1) * 32;
    int o_base = blockIdx.x * 128;
    int n_base = blockIdx.y * 128;
    int b = blockIdx.z;

    const __half* Ap = ((WHICH == 0) ? g_wqc : g_wpc) + (size_t)o_base*256;
    const __half* Bp = ((WHICH == 0) ? g_xlt : g_xat) + ((size_t)b*NTOT + n_base)*256;

    float acc[4][4][4];
    #pragma unroll
    for (int mi = 0; mi < 4; ++mi)
        #pragma unroll
        for (int nj = 0; nj < 4; ++nj)
            #pragma unroll
            for (int q = 0; q < 4; ++q) acc[mi][nj][q] = 0.f;

    auto stage = [&](int chunk, int buf) {
        int c0 = chunk * KC;
        uint32_t ab = sb + (uint32_t)buf * (2*TFH*2);
        uint32_t bbuf = ab + TFH*2;
        #pragma unroll
        for (int t = 0; t < KC/16; ++t) {
            int g = tid + t*256; int row = g / (KC/8), j = g % (KC/8);
            cpasync16(ab + row*ROWB + j*16, Ap + (size_t)row*256 + c0 + j*8);
            cpasync16(bbuf + row*ROWB + j*16, Bp + (size_t)row*256 + c0 + j*8);
        }
        cp_commit();
    };

    constexpr int NCH = 256/KC;
    stage(0, 0);
    for (int i = 0; i < NCH; ++i) {
        int buf = i & 1;
        if (i < NCH-1) stage(i + 1, buf ^ 1);
        if (i < NCH-1) cp_wait1(); else cp_wait0();
        __syncthreads();
        uint32_t ab = sb + (uint32_t)buf * (2*TFH*2);
        compute_chunk<KC>(ab, ab + TFH*2, wm, wn, lane, acc);
        __syncthreads();
    }

    int lr = lane >> 2, lc = lane & 3;
    #pragma unroll
    for (int mi = 0; mi < 4; ++mi) {
        int o0 = o_base + wm + mi*16 + lr;
        float bv0 = bias[o0], bv1 = bias[o0 + 8];
        #pragma unroll
        for (int nj = 0; nj < 4; ++nj) {
            int col = wn + nj*8 + lc*2;
            if (WHICH == 0) {
                __half* y0 = g_qkv + ((size_t)b*OC + o0)*NTOT + n_base;
                __half* y1 = g_qkv + ((size_t)b*OC + o0 + 8)*NTOT + n_base;
                *(__half2*)(y0 + col) = __floats2half2_rn(acc[mi][nj][0] + bv0, acc[mi][nj][1] + bv0);
                *(__half2*)(y1 + col) = __floats2half2_rn(acc[mi][nj][2] + bv1, acc[mi][nj][3] + bv1);
            } else {
                float* y0 = Yext + ((size_t)b*OC + o0)*NTOT + n_base;
                float* y1 = Yext + ((size_t)b*OC + o0 + 8)*NTOT + n_base;
                float2 v0 = { acc[mi][nj][0] + bv0, acc[mi][nj][1] + bv0 };
                float2 v1 = { acc[mi][nj][2] + bv1, acc[mi][nj][3] + bv1 };
                *(float2*)(y0 + col) = v0;
                *(float2*)(y1 + col) = v1;
            }
        }
    }
}

// ================= attention (fp32 math on packed f32x2; fp16 in/out) =================
__global__ __launch_bounds__(64) void attn_kernel(const float* __restrict__ rpb) {
    __shared__ float qs[2048];
    __shared__ float ks[2048];
    __shared__ float vs[2048];
    __shared__ float rpb_s[225];

    int head = blockIdx.x, d = blockIdx.y, b = blockIdx.z;
    int t = threadIdx.x;

    const __half* base = g_qkv + ((size_t)(b*O3 + head*HDIM))*NTOT + d*64;
    for (int i = t; i < 2048; i += 64) {
        int hd = i >> 6, n = i & 63;
        qs[i] = __half2float(base[(size_t)hd*NTOT + n]);
        ks[i] = __half2float(base[(size_t)(256 + hd)*NTOT + n]);
        vs[i] = __half2float(base[(size_t)(512 + hd)*NTOT + n]);
    }
    for (int i = t; i < 225; i += 64) rpb_s[i] = rpb[i*HEADS + head];
    __syncthreads();

    const int n = t, hn = n >> 3, wn = n & 7;
    const float scale = 0.17677669529663687f;

    u64t acc2[32];
    #pragma unroll
    for (int j = 0; j < 32; ++j) acc2[j] = 0ull;
    #pragma unroll
    for (int hd = 0; hd < 32; ++hd) {
        float qv = qs[hd*64 + n];
        u64t qd = pk2(qv, qv);
        const ulonglong2* kp = (const ulonglong2*)&ks[hd*64];
        #pragma unroll
        for (int m4 = 0; m4 < 16; ++m4) {
            ulonglong2 kk = kp[m4];
            fma2(acc2[m4*2],     qd, kk.x);
            fma2(acc2[m4*2 + 1], qd, kk.y);
        }
    }

    float sc[64];
    #pragma unroll
    for (int j = 0; j < 32; ++j) upk2(acc2[j], sc[2*j], sc[2*j + 1]);
    #pragma unroll
    for (int m = 0; m < 64; ++m) {
        int di = hn - (m >> 3) + 7;
        int dj = wn - (m & 7) + 7;
        sc[m] = sc[m]*scale + rpb_s[di*15 + dj];
    }

    float mx = -1e30f;
    #pragma unroll
    for (int m = 0; m < 64; ++m) mx = fmaxf(mx, sc[m]);
    float sum = 0.f;
    #pragma unroll
    for (int m = 0; m < 64; ++m) { sc[m] = __expf(sc[m] - mx); sum += sc[m]; }
    float inv = 1.f / sum;

    #pragma unroll
    for (int j = 0; j < 32; ++j) acc2[j] = pk2(sc[2*j]*inv, sc[2*j + 1]*inv);

    __half* ysl = g_xat + ((size_t)(b*NTOT + d*64 + n))*CC + head*HDIM;
    #pragma unroll
    for (int hd4 = 0; hd4 < 8; ++hd4) {
        float op[4];
        #pragma unroll
        for (int q = 0; q < 4; ++q) {
            int hd = hd4*4 + q;
            u64t o2 = 0ull;
            const ulonglong2* vp = (const ulonglong2*)&vs[hd*64];
            #pragma unroll
            for (int m4 = 0; m4 < 16; ++m4) {
                ulonglong2 vv = vp[m4];
                fma2(o2, acc2[m4*2],     vv.x);
                fma2(o2, acc2[m4*2 + 1], vv.y);
            }
            float lo, hi; upk2(o2, lo, hi);
            op[q] = lo + hi;
        }
        *(__half2*)(ysl + hd4*4)     = __floats2half2_rn(op[0], op[1]);
        *(__half2*)(ysl + hd4*4 + 2) = __floats2half2_rn(op[2], op[3]);
    }
}

// ================= launch =================
extern "C" void kernel_launch(void* const* d_in, const int* in_sizes, int n_in,
                              void* d_out, int out_size) {
    const float* x   = (const float*)d_in[0];
    const float* dw  = (const float*)d_in[1];
    const float* dwb = (const float*)d_in[2];
    const float* qw  = (const float*)d_in[3];
    const float* qb  = (const float*)d_in[4];
    const float* pw  = (const float*)d_in[5];
    const float* pb  = (const float*)d_in[6];
    const float* rpb = (const float*)d_in[7];
    float* out = (float*)d_out;

    const int BIG = TC<64>::SMEMB;   // 73728 (covers CV_SMEM=65664 too)
    bool big = true;
    big &= cudaFuncSetAttribute(conv_mma2, cudaFuncAttributeMaxDynamicSharedMemorySize, BIG) == cudaSuccess;
    big &= cudaFuncSetAttribute(gemm_mma<O3,0,64>, cudaFuncAttributeMaxDynamicSharedMemorySize, BIG) == cudaSuccess;
    big &= cudaFuncSetAttribute(gemm_mma<CC,1,64>, cudaFuncAttributeMaxDynamicSharedMemorySize, BIG) == cudaSuccess;

    prep_weights<<<(9*CC*CC + 255)/256, 256>>>(dw, qw, pw);
    pad_transpose<<<dim3(DD, BB), 256>>>(x);
    if (big) {
        conv_mma2<<<dim3(2, 50, BB), 256, CV_SMEM>>>(dwb);
        gemm_mma<O3,0,64><<<dim3(6, 50, BB), 256, BIG>>>(qb, nullptr);
    } else {
        conv_mma<32><<<dim3(2, 50, BB), 256, TC<32>::SMEMB>>>(dwb);
        gemm_mma<O3,0,32><<<dim3(6, 50, BB), 256, TC<32>::SMEMB>>>(qb, nullptr);
    }
    attn_kernel<<<dim3(HEADS, DD, BB), 64>>>(rpb);
    if (big) {
        gemm_mma<CC,1,64><<<dim3(2, 50, BB), 256, BIG>>>(pb, out);
    } else {
        gemm_mma<CC,1,32><<<dim3(2, 50, BB), 256, TC<32>::SMEMB>>>(pb, out);
    }
}

// round 13
// speedup vs baseline: 5.8620x; 1.0352x over previous
#include <cuda_runtime.h>
#include <cuda_fp16.h>
#include <cstdint>

// ---------------- problem constants ----------------
#define BB 8
#define CC 256
#define DD 100
#define NN 64
#define HEADS 8
#define HDIM 32
#define O3 768
#define NTOT 6400      // D*N per batch

// ---------------- device scratch (referenced ONLY from device code) ----------------
__device__ __half g_xp  [BB*DD*100*CC];  // padded transposed input [b][d][p100][c]
__device__ __half g_xlt [BB*NTOT*CC];    // conv out transposed [b][n][c]
__device__ __half g_qkv [BB*O3*NTOT];    // qkv [b][o][ntot]
__device__ __half g_xat [BB*NTOT*CC];    // attn out transposed [b][n][c]
__device__ __half g_wconv[9*CC*CC];      // [k][o][c]
__device__ __half g_wqc [O3*CC];         // qkv_w
__device__ __half g_wpc [CC*CC];         // proj_w

// ---------------- helpers ----------------
typedef unsigned long long u64t;

__device__ __forceinline__ uint32_t smem_u32(const void* p) {
    uint32_t a;
    asm("{ .reg .u64 t; cvta.to.shared.u64 t, %1; cvt.u32.u64 %0, t; }" : "=r"(a) : "l"(p));
    return a;
}
__device__ __forceinline__ void cpasync16(uint32_t dst, const void* src) {
    asm volatile("cp.async.cg.shared.global [%0], [%1], 16;" :: "r"(dst), "l"(src) : "memory");
}
__device__ __forceinline__ void cp_commit() { asm volatile("cp.async.commit_group;" ::: "memory"); }
__device__ __forceinline__ void cp_wait1()  { asm volatile("cp.async.wait_group 1;" ::: "memory"); }
__device__ __forceinline__ void cp_wait0()  { asm volatile("cp.async.wait_group 0;" ::: "memory"); }

__device__ __forceinline__ u64t pk2(float lo, float hi) {
    u64t r; asm("mov.b64 %0,{%1,%2};" : "=l"(r) : "f"(lo), "f"(hi)); return r;
}
__device__ __forceinline__ void fma2(u64t& d, u64t a, u64t b) {
    asm("fma.rn.f32x2 %0,%1,%2,%0;" : "+l"(d) : "l"(a), "l"(b));
}
__device__ __forceinline__ void upk2(u64t v, float& lo, float& hi) {
    asm("mov.b64 {%0,%1},%2;" : "=f"(lo), "=f"(hi) : "l"(v));
}

__device__ __forceinline__ void mma_f16(float c[4], const uint32_t a[4], const uint32_t b[2]) {
    asm volatile(
        "mma.sync.aligned.m16n8k16.row.col.f32.f16.f16.f32 "
        "{%0,%1,%2,%3}, {%4,%5,%6,%7}, {%8,%9}, {%0,%1,%2,%3};"
        : "+f"(c[0]), "+f"(c[1]), "+f"(c[2]), "+f"(c[3])
        : "r"(a[0]), "r"(a[1]), "r"(a[2]), "r"(a[3]), "r"(b[0]), "r"(b[1]));
}
__device__ __forceinline__ void ldsm_x4(uint32_t& r0, uint32_t& r1, uint32_t& r2, uint32_t& r3,
                                        uint32_t addr) {
    asm volatile("ldmatrix.sync.aligned.m8n8.x4.shared.b16 {%0,%1,%2,%3}, [%4];"
                 : "=r"(r0), "=r"(r1), "=r"(r2), "=r"(r3) : "r"(addr));
}

// generic GEMM tiles: 128 rows x KC halves; row stride KC+8 halves
template<int KC> struct TC {
    static constexpr int STRH  = KC + 8;
    static constexpr int TFH   = 128 * STRH;
    static constexpr int SMEMB = 4 * TFH * 2;
};

// warp-tile MMA over one staged 128xKC half chunk pair; ldmatrix fragment loads
template<int KC>
__device__ __forceinline__ void compute_chunk(uint32_t As, uint32_t Bs,
                                              int wm, int wn, int lane,
                                              float acc[4][4][4]) {
    constexpr int STRH = TC<KC>::STRH;
    int arow = lane & 15, akoff = (lane >> 4) * 8;
    int brow = (lane & 7) + (lane >> 4) * 8, bkoff = ((lane >> 3) & 1) * 8;
    #pragma unroll
    for (int ks = 0; ks < KC/16; ++ks) {
        int k0 = ks*16;
        uint32_t a[4][4];
        #pragma unroll
        for (int mi = 0; mi < 4; ++mi)
            ldsm_x4(a[mi][0], a[mi][1], a[mi][2], a[mi][3],
                    As + (((wm + mi*16 + arow)*STRH) + k0 + akoff)*2);
        uint32_t bf[4][2];
        #pragma unroll
        for (int njp = 0; njp < 2; ++njp)
            ldsm_x4(bf[njp*2][0], bf[njp*2][1], bf[njp*2+1][0], bf[njp*2+1][1],
                    Bs + (((wn + njp*16 + brow)*STRH) + k0 + bkoff)*2);
        #pragma unroll
        for (int mi = 0; mi < 4; ++mi)
            #pragma unroll
            for (int nj = 0; nj < 4; ++nj)
                mma_f16(acc[mi][nj], a[mi], bf[nj]);
    }
}

// ================= pre-passes =================
__global__ void prep_weights(const float* __restrict__ dw,
                             const float* __restrict__ qw,
                             const float* __restrict__ pw) {
    int i = blockIdx.x * blockDim.x + threadIdx.x;
    if (i < 9*CC*CC) {
        int c = i & 255, o = (i >> 8) & 255, k = i >> 16;
        g_wconv[i] = __float2half(dw[(o*CC + c)*9 + k]);
    }
    if (i < O3*CC) g_wqc[i] = __float2half(qw[i]);
    if (i < CC*CC) g_wpc[i] = __float2half(pw[i]);
}

__global__ __launch_bounds__(256) void pad_transpose(const float* __restrict__ x) {
    __shared__ float Xs[64][65];
    int d = blockIdx.x, b = blockIdx.y, t = threadIdx.x;
    __half* outb = g_xp + ((size_t)(b*DD + d)) * 100 * CC;
    for (int cc = 0; cc < 4; ++cc) {
        int c_base = cc * 64;
        __syncthreads();
        for (int v = t; v < 4096; v += 256) {
            int c = v >> 6, n = v & 63;
            Xs[c][n] = x[((size_t)(b*CC + c_base + c)*DD + d)*64 + n];
        }
        __syncthreads();
        for (int v = t; v < 6400; v += 256) {
            int p = v >> 6, c = v & 63;
            int h = p/10 - 1, w = p%10 - 1;
            float val = 0.f;
            if ((unsigned)h < 8u && (unsigned)w < 8u) val = Xs[c][h*8 + w];
            outb[p*CC + c_base + c] = __float2half(val);
        }
    }
}

// ================= conv v3: resident slab + TRIPLE-buffered W, 1 sync per shift =========
#define CV_STRH 72
#define CV_SLABB 28800
#define CV_WB    18432
#define CV_SMEM3 (CV_SLABB + 3*CV_WB)    // 84096

__global__ __launch_bounds__(256) void conv_mma3(const float* __restrict__ bconv) {
    extern __shared__ __half smemh[];
    uint32_t sb = smem_u32(smemh);
    const uint32_t SLAB = sb;
    uint32_t wbuf[3] = { sb + CV_SLABB, sb + CV_SLABB + CV_WB, sb + CV_SLABB + 2*CV_WB };
    int tid = threadIdx.x, lane = tid & 31, wid = tid >> 5;
    int wm = (wid & 1) * 64, wn = (wid >> 1) * 32;
    int o_base = blockIdx.x * 128;
    int d0 = blockIdx.y * 2;
    int b = blockIdx.z;

    const __half* xpb = g_xp + ((size_t)(b*DD + d0)) * 25600;

    int arowl = lane & 15, akoff = (lane >> 4) * 8;
    uint32_t abase[4];
    #pragma unroll
    for (int mi = 0; mi < 4; ++mi) {
        int m = wm + mi*16 + arowl;
        int slabrow = (m >> 6)*100 + ((m & 63) >> 3)*10 + (m & 7);
        abase[mi] = SLAB + (slabrow*CV_STRH + akoff)*2;
    }
    int brow = (lane & 7) + (lane >> 4) * 8, bkoff = ((lane >> 3) & 1) * 8;

    float acc[4][4][4];
    #pragma unroll
    for (int mi = 0; mi < 4; ++mi)
        #pragma unroll
        for (int nj = 0; nj < 4; ++nj)
            #pragma unroll
            for (int q = 0; q < 4; ++q) acc[mi][nj][q] = 0.f;

    for (int cc = 0; cc < 4; ++cc) {
        int c0 = cc * 64;
        __syncthreads();                       // all prior slab/W consumption done
        #pragma unroll
        for (int t = 0; t < 7; ++t) {          // slab: 200 rows x 8 segs = 1600
            int s = tid + t*256;
            if (s < 1600) {
                int row = s >> 3, j = s & 7;
                cpasync16(SLAB + row*144 + j*16,
                          xpb + (size_t)(row/100)*25600 + (row%100)*256 + c0 + j*8);
            }
        }
        cp_commit();
        auto stageW = [&](int k, uint32_t wb) {
            const __half* wkb = g_wconv + k*65536 + (size_t)o_base*256 + c0;
            #pragma unroll
            for (int t = 0; t < 4; ++t) {
                int s = tid + t*256; int row = s >> 3, j = s & 7;
                cpasync16(wb + row*144 + j*16, wkb + row*256 + j*8);
            }
            cp_commit();
        };
        stageW(0, wbuf[0]);
        stageW(1, wbuf[1]);
        for (int k = 0; k < 9; ++k) {
            if (k < 8) cp_wait1(); else cp_wait0();   // slab + W(k) done
            __syncthreads();                          // buf (k+2)%3 fully consumed (iter k-1)
            if (k + 2 < 9) stageW(k + 2, wbuf[(k + 2) % 3]);
            uint32_t wb = wbuf[k % 3];
            uint32_t shoff = (uint32_t)((k/3)*10 + (k%3)) * 144;
            #pragma unroll
            for (int ks = 0; ks < 4; ++ks) {
                int k0 = ks*16;
                uint32_t a[4][4];
                #pragma unroll
                for (int mi = 0; mi < 4; ++mi)
                    ldsm_x4(a[mi][0], a[mi][1], a[mi][2], a[mi][3],
                            abase[mi] + shoff + k0*2);
                uint32_t bf[4][2];
                #pragma unroll
                for (int njp = 0; njp < 2; ++njp)
                    ldsm_x4(bf[njp*2][0], bf[njp*2][1], bf[njp*2+1][0], bf[njp*2+1][1],
                            wb + (((wn + njp*16 + brow)*CV_STRH) + k0 + bkoff)*2);
                #pragma unroll
                for (int mi = 0; mi < 4; ++mi)
                    #pragma unroll
                    for (int nj = 0; nj < 4; ++nj)
                        mma_f16(acc[mi][nj], a[mi], bf[nj]);
            }
        }
    }

    int lr = lane >> 2, lc = lane & 3;
    #pragma unroll
    for (int mi = 0; mi < 4; ++mi) {
        int m = wm + mi*16 + lr;
        int ng0 = (d0 + (m >> 6))*64 + (m & 63);
        int ng1 = (d0 + ((m+8) >> 6))*64 + ((m+8) & 63);
        __half* r0 = g_xlt + ((size_t)(b*NTOT + ng0))*CC + o_base;
        __half* r1 = g_xlt + ((size_t)(b*NTOT + ng1))*CC + o_base;
        #pragma unroll
        for (int nj = 0; nj < 4; ++nj) {
            int o = wn + nj*8 + lc*2;
            float bv0 = bconv[o_base + o], bv1 = bconv[o_base + o + 1];
            *(__half2*)(r0 + o) = __floats2half2_rn(acc[mi][nj][0] + bv0, acc[mi][nj][1] + bv1);
            *(__half2*)(r1 + o) = __floats2half2_rn(acc[mi][nj][2] + bv0, acc[mi][nj][3] + bv1);
        }
    }
}

// ================= projection GEMM v3: 3-stage multistage, 1 sync per chunk =============
// WHICH==0: A=g_wqc, B=g_xlt, Y=g_qkv(half).  WHICH==1: A=g_wpc, B=g_xat, Y=Yext(float).
#define G3_STRH 72
#define G3_TFH  (128*G3_STRH)
#define G3_STAGEB (2*G3_TFH*2)           // A+B per stage = 36864
#define G3_SMEM (3*G3_STAGEB)            // 110592

template<int OC, int WHICH>
__global__ __launch_bounds__(256) void gemm_mma3(const float* __restrict__ bias,
                                                 float* __restrict__ Yext) {
    extern __shared__ __half smemh[];
    uint32_t sb = smem_u32(smemh);
    int tid = threadIdx.x, lane = tid & 31, wid = tid >> 5;
    int wm = (wid & 1) * 64, wn = (wid >> 1) * 32;
    int o_base = blockIdx.x * 128;
    int n_base = blockIdx.y * 128;
    int b = blockIdx.z;

    const __half* Ap = ((WHICH == 0) ? g_wqc : g_wpc) + (size_t)o_base*256;
    const __half* Bp = ((WHICH == 0) ? g_xlt : g_xat) + ((size_t)b*NTOT + n_base)*256;

    float acc[4][4][4];
    #pragma unroll
    for (int mi = 0; mi < 4; ++mi)
        #pragma unroll
        for (int nj = 0; nj < 4; ++nj)
            #pragma unroll
            for (int q = 0; q < 4; ++q) acc[mi][nj][q] = 0.f;

    auto stage = [&](int chunk, int s) {
        int c0 = chunk * 64;
        uint32_t ab = sb + (uint32_t)s * G3_STAGEB;
        uint32_t bbuf = ab + G3_TFH*2;
        #pragma unroll
        for (int t = 0; t < 4; ++t) {
            int g = tid + t*256; int row = g >> 3, j = g & 7;
            cpasync16(ab + row*144 + j*16, Ap + (size_t)row*256 + c0 + j*8);
            cpasync16(bbuf + row*144 + j*16, Bp + (size_t)row*256 + c0 + j*8);
        }
        cp_commit();
    };

    stage(0, 0);
    stage(1, 1);
    #pragma unroll
    for (int i = 0; i < 4; ++i) {
        if (i < 3) cp_wait1(); else cp_wait0();
        __syncthreads();                       // buf (i+2)%3 fully consumed (iter i-1)
        if (i + 2 < 4) stage(i + 2, (i + 2) % 3);
        uint32_t ab = sb + (uint32_t)(i % 3) * G3_STAGEB;
        compute_chunk<64>(ab, ab + G3_TFH*2, wm, wn, lane, acc);
    }

    int lr = lane >> 2, lc = lane & 3;
    #pragma unroll
    for (int mi = 0; mi < 4; ++mi) {
        int o0 = o_base + wm + mi*16 + lr;
        float bv0 = bias[o0], bv1 = bias[o0 + 8];
        #pragma unroll
        for (int nj = 0; nj < 4; ++nj) {
            int col = wn + nj*8 + lc*2;
            if (WHICH == 0) {
                __half* y0 = g_qkv + ((size_t)b*OC + o0)*NTOT + n_base;
                __half* y1 = g_qkv + ((size_t)b*OC + o0 + 8)*NTOT + n_base;
                *(__half2*)(y0 + col) = __floats2half2_rn(acc[mi][nj][0] + bv0, acc[mi][nj][1] + bv0);
                *(__half2*)(y1 + col) = __floats2half2_rn(acc[mi][nj][2] + bv1, acc[mi][nj][3] + bv1);
            } else {
                float* y0 = Yext + ((size_t)b*OC + o0)*NTOT + n_base;
                float* y1 = Yext + ((size_t)b*OC + o0 + 8)*NTOT + n_base;
                float2 v0 = { acc[mi][nj][0] + bv0, acc[mi][nj][1] + bv0 };
                float2 v1 = { acc[mi][nj][2] + bv1, acc[mi][nj][3] + bv1 };
                *(float2*)(y0 + col) = v0;
                *(float2*)(y1 + col) = v1;
            }
        }
    }
}

// ================= KC=32 2-stage fallbacks (40KB smem, no opt-in) =================
template<int KC>
__global__ __launch_bounds__(256) void conv_mma(const float* __restrict__ bconv) {
    constexpr int TFH  = TC<KC>::TFH;
    constexpr int ROWB = TC<KC>::STRH * 2;
    extern __shared__ __half smemh[];
    uint32_t sb = smem_u32(smemh);
    int tid = threadIdx.x, lane = tid & 31, wid = tid >> 5;
    int wm = (wid & 1) * 64, wn = (wid >> 1) * 32;
    int o_base = blockIdx.x * 128;
    int d0 = blockIdx.y * 2;
    int b = blockIdx.z;

    const __half* xpb = g_xp + ((size_t)(b*DD + d0)) * 25600;

    float acc[4][4][4];
    #pragma unroll
    for (int mi = 0; mi < 4; ++mi)
        #pragma unroll
        for (int nj = 0; nj < 4; ++nj)
            #pragma unroll
            for (int q = 0; q < 4; ++q) acc[mi][nj][q] = 0.f;

    constexpr int CPK = 256/KC;
    auto stage = [&](int chunk, int buf) {
        int k = chunk / CPK, c0 = (chunk % CPK) * KC;
        int kh = k / 3, kw = k % 3;
        uint32_t ab = sb + (uint32_t)buf * (2*TFH*2);
        uint32_t bbuf = ab + TFH*2;
        const __half* wkb = g_wconv + k*65536 + (size_t)o_base*256 + c0;
        #pragma unroll
        for (int t = 0; t < KC/16; ++t) {
            int g = tid + t*256; int row = g / (KC/8), j = g % (KC/8);
            int dl = row >> 6, n = row & 63, h = n >> 3, w = n & 7;
            int p = (h + kh)*10 + (w + kw);
            cpasync16(ab + row*ROWB + j*16, xpb + (size_t)dl*25600 + p*256 + c0 + j*8);
            cpasync16(bbuf + row*ROWB + j*16, wkb + row*256 + j*8);
        }
        cp_commit();
    };

    constexpr int NCH = 9 * CPK;
    stage(0, 0);
    for (int i = 0; i < NCH; ++i) {
        int buf = i & 1;
        if (i < NCH-1) stage(i + 1, buf ^ 1);
        if (i < NCH-1) cp_wait1(); else cp_wait0();
        __syncthreads();
        uint32_t ab = sb + (uint32_t)buf * (2*TFH*2);
        compute_chunk<KC>(ab, ab + TFH*2, wm, wn, lane, acc);
        __syncthreads();
    }

    int lr = lane >> 2, lc = lane & 3;
    #pragma unroll
    for (int mi = 0; mi < 4; ++mi) {
        int m = wm + mi*16 + lr;
        int ng0 = (d0 + (m >> 6))*64 + (m & 63);
        int ng1 = (d0 + ((m+8) >> 6))*64 + ((m+8) & 63);
        __half* r0 = g_xlt + ((size_t)(b*NTOT + ng0))*CC + o_base;
        __half* r1 = g_xlt + ((size_t)(b*NTOT + ng1))*CC + o_base;
        #pragma unroll
        for (int nj = 0; nj < 4; ++nj) {
            int o = wn + nj*8 + lc*2;
            float bv0 = bconv[o_base + o], bv1 = bconv[o_base + o + 1];
            *(__half2*)(r0 + o) = __floats2half2_rn(acc[mi][nj][0] + bv0, acc[mi][nj][1] + bv1);
            *(__half2*)(r1 + o) = __floats2half2_rn(acc[mi][nj][2] + bv0, acc[mi][nj][3] + bv1);
        }
    }
}

template<int OC, int WHICH, int KC>
__global__ __launch_bounds__(256) void gemm_mma(const float* __restrict__ bias,
                                                float* __restrict__ Yext) {
    constexpr int TFH  = TC<KC>::TFH;
    constexpr int ROWB = TC<KC>::STRH * 2;
    extern __shared__ __half smemh[];
    uint32_t sb = smem_u32(smemh);
    int tid = threadIdx.x, lane = tid & 31, wid = tid >> 5;
    int wm = (wid & 1) * 64, wn = (wid >> 1) * 32;
    int o_base = blockIdx.x * 128;
    int n_base = blockIdx.y * 128;
    int b = blockIdx.z;

    const __half* Ap = ((WHICH == 0) ? g_wqc : g_wpc) + (size_t)o_base*256;
    const __half* Bp = ((WHICH == 0) ? g_xlt : g_xat) + ((size_t)b*NTOT + n_base)*256;

    float acc[4][4][4];
    #pragma unroll
    for (int mi = 0; mi < 4; ++mi)
        #pragma unroll
        for (int nj = 0; nj < 4; ++nj)
            #pragma unroll
            for (int q = 0; q < 4; ++q) acc[mi][nj][q] = 0.f;

    auto stage = [&](int chunk, int buf) {
        int c0 = chunk * KC;
        uint32_t ab = sb + (uint32_t)buf * (2*TFH*2);
        uint32_t bbuf = ab + TFH*2;
        #pragma unroll
        for (int t = 0; t < KC/16; ++t) {
            int g = tid + t*256; int row = g / (KC/8), j = g % (KC/8);
            cpasync16(ab + row*ROWB + j*16, Ap + (size_t)row*256 + c0 + j*8);
            cpasync16(bbuf + row*ROWB + j*16, Bp + (size_t)row*256 + c0 + j*8);
        }
        cp_commit();
    };

    constexpr int NCH = 256/KC;
    stage(0, 0);
    for (int i = 0; i < NCH; ++i) {
        int buf = i & 1;
        if (i < NCH-1) stage(i + 1, buf ^ 1);
        if (i < NCH-1) cp_wait1(); else cp_wait0();
        __syncthreads();
        uint32_t ab = sb + (uint32_t)buf * (2*TFH*2);
        compute_chunk<KC>(ab, ab + TFH*2, wm, wn, lane, acc);
        __syncthreads();
    }

    int lr = lane >> 2, lc = lane & 3;
    #pragma unroll
    for (int mi = 0; mi < 4; ++mi) {
        int o0 = o_base + wm + mi*16 + lr;
        float bv0 = bias[o0], bv1 = bias[o0 + 8];
        #pragma unroll
        for (int nj = 0; nj < 4; ++nj) {
            int col = wn + nj*8 + lc*2;
            if (WHICH == 0) {
                __half* y0 = g_qkv + ((size_t)b*OC + o0)*NTOT + n_base;
                __half* y1 = g_qkv + ((size_t)b*OC + o0 + 8)*NTOT + n_base;
                *(__half2*)(y0 + col) = __floats2half2_rn(acc[mi][nj][0] + bv0, acc[mi][nj][1] + bv0);
                *(__half2*)(y1 + col) = __floats2half2_rn(acc[mi][nj][2] + bv1, acc[mi][nj][3] + bv1);
            } else {
                float* y0 = Yext + ((size_t)b*OC + o0)*NTOT + n_base;
                float* y1 = Yext + ((size_t)b*OC + o0 + 8)*NTOT + n_base;
                float2 v0 = { acc[mi][nj][0] + bv0, acc[mi][nj][1] + bv0 };
                float2 v1 = { acc[mi][nj][2] + bv1, acc[mi][nj][3] + bv1 };
                *(float2*)(y0 + col) = v0;
                *(float2*)(y1 + col) = v1;
            }
        }
    }
}

// ================= attention (fp32 math on packed f32x2; fp16 in/out) =================
__global__ __launch_bounds__(64) void attn_kernel(const float* __restrict__ rpb) {
    __shared__ float qs[2048];
    __shared__ float ks[2048];
    __shared__ float vs[2048];
    __shared__ float rpb_s[225];

    int head = blockIdx.x, d = blockIdx.y, b = blockIdx.z;
    int t = threadIdx.x;

    const __half* base = g_qkv + ((size_t)(b*O3 + head*HDIM))*NTOT + d*64;
    for (int i = t; i < 2048; i += 64) {
        int hd = i >> 6, n = i & 63;
        qs[i] = __half2float(base[(size_t)hd*NTOT + n]);
        ks[i] = __half2float(base[(size_t)(256 + hd)*NTOT + n]);
        vs[i] = __half2float(base[(size_t)(512 + hd)*NTOT + n]);
    }
    for (int i = t; i < 225; i += 64) rpb_s[i] = rpb[i*HEADS + head];
    __syncthreads();

    const int n = t, hn = n >> 3, wn = n & 7;
    const float scale = 0.17677669529663687f;

    u64t acc2[32];
    #pragma unroll
    for (int j = 0; j < 32; ++j) acc2[j] = 0ull;
    #pragma unroll
    for (int hd = 0; hd < 32; ++hd) {
        float qv = qs[hd*64 + n];
        u64t qd = pk2(qv, qv);
        const ulonglong2* kp = (const ulonglong2*)&ks[hd*64];
        #pragma unroll
        for (int m4 = 0; m4 < 16; ++m4) {
            ulonglong2 kk = kp[m4];
            fma2(acc2[m4*2],     qd, kk.x);
            fma2(acc2[m4*2 + 1], qd, kk.y);
        }
    }

    float sc[64];
    #pragma unroll
    for (int j = 0; j < 32; ++j) upk2(acc2[j], sc[2*j], sc[2*j + 1]);
    #pragma unroll
    for (int m = 0; m < 64; ++m) {
        int di = hn - (m >> 3) + 7;
        int dj = wn - (m & 7) + 7;
        sc[m] = sc[m]*scale + rpb_s[di*15 + dj];
    }

    float mx = -1e30f;
    #pragma unroll
    for (int m = 0; m < 64; ++m) mx = fmaxf(mx, sc[m]);
    float sum = 0.f;
    #pragma unroll
    for (int m = 0; m < 64; ++m) { sc[m] = __expf(sc[m] - mx); sum += sc[m]; }
    float inv = 1.f / sum;

    #pragma unroll
    for (int j = 0; j < 32; ++j) acc2[j] = pk2(sc[2*j]*inv, sc[2*j + 1]*inv);

    __half* ysl = g_xat + ((size_t)(b*NTOT + d*64 + n))*CC + head*HDIM;
    #pragma unroll
    for (int hd4 = 0; hd4 < 8; ++hd4) {
        float op[4];
        #pragma unroll
        for (int q = 0; q < 4; ++q) {
            int hd = hd4*4 + q;
            u64t o2 = 0ull;
            const ulonglong2* vp = (const ulonglong2*)&vs[hd*64];
            #pragma unroll
            for (int m4 = 0; m4 < 16; ++m4) {
                ulonglong2 vv = vp[m4];
                fma2(o2, acc2[m4*2],     vv.x);
                fma2(o2, acc2[m4*2 + 1], vv.y);
            }
            float lo, hi; upk2(o2, lo, hi);
            op[q] = lo + hi;
        }
        *(__half2*)(ysl + hd4*4)     = __floats2half2_rn(op[0], op[1]);
        *(__half2*)(ysl + hd4*4 + 2) = __floats2half2_rn(op[2], op[3]);
    }
}

// ================= launch =================
extern "C" void kernel_launch(void* const* d_in, const int* in_sizes, int n_in,
                              void* d_out, int out_size) {
    const float* x   = (const float*)d_in[0];
    const float* dw  = (const float*)d_in[1];
    const float* dwb = (const float*)d_in[2];
    const float* qw  = (const float*)d_in[3];
    const float* qb  = (const float*)d_in[4];
    const float* pw  = (const float*)d_in[5];
    const float* pb  = (const float*)d_in[6];
    const float* rpb = (const float*)d_in[7];
    float* out = (float*)d_out;

    bool big = true;
    big &= cudaFuncSetAttribute(conv_mma3, cudaFuncAttributeMaxDynamicSharedMemorySize, CV_SMEM3) == cudaSuccess;
    big &= cudaFuncSetAttribute(gemm_mma3<O3,0>, cudaFuncAttributeMaxDynamicSharedMemorySize, G3_SMEM) == cudaSuccess;
    big &= cudaFuncSetAttribute(gemm_mma3<CC,1>, cudaFuncAttributeMaxDynamicSharedMemorySize, G3_SMEM) == cudaSuccess;

    prep_weights<<<(9*CC*CC + 255)/256, 256>>>(dw, qw, pw);
    pad_transpose<<<dim3(DD, BB), 256>>>(x);
    if (big) {
        conv_mma3<<<dim3(2, 50, BB), 256, CV_SMEM3>>>(dwb);
        gemm_mma3<O3,0><<<dim3(6, 50, BB), 256, G3_SMEM>>>(qb, nullptr);
    } else {
        conv_mma<32><<<dim3(2, 50, BB), 256, TC<32>::SMEMB>>>(dwb);
        gemm_mma<O3,0,32><<<dim3(6, 50, BB), 256, TC<32>::SMEMB>>>(qb, nullptr);
    }
    attn_kernel<<<dim3(HEADS, DD, BB), 64>>>(rpb);
    if (big) {
        gemm_mma3<CC,1><<<dim3(2, 50, BB), 256, G3_SMEM>>>(pb, out);
    } else {
        gemm_mma<CC,1,32><<<dim3(2, 50, BB), 256, TC<32>::SMEMB>>>(pb, out);
    }
}